// round 1
// baseline (speedup 1.0000x reference)
#include <cuda_runtime.h>

#define B_  4
#define S_  1024
#define DM_ 1024
#define H_  16
#define D_  64
#define SE_ 512
#define DF_ 512

// ---------------- scratch (static device arrays; no allocations) ----------------
__device__ float g_Q [B_*H_*S_ *D_];   // [B,H,S,D]
__device__ float g_K [B_*H_*S_ *D_];
__device__ float g_V [B_*H_*S_ *D_];
__device__ float g_FK[B_*H_*SE_*D_];   // [B,H,SE,D]
__device__ float g_FV[B_*H_*SE_*D_];
__device__ float g_CTX[B_*S_*DM_];     // [B,S,H*D] merged heads
__device__ float g_Y  [B_*S_*DM_];     // pre-LN

// ---------------- generic projection GEMM: C = A[M,K] @ W[N,K]^T + bias --------
// out scattered to split-head layout [B,H,Sx,D]; which selects destination.
__global__ void k_proj(const float* __restrict__ A, const float* __restrict__ W,
                       const float* __restrict__ bias, int which,
                       int K, int Sx) {
    __shared__ float As[16][68];
    __shared__ float Ws[16][68];
    const int tid = threadIdx.x;
    const int tx = tid & 15, ty = tid >> 4;
    const int m0 = blockIdx.y * 64, n0 = blockIdx.x * 64;
    float acc[4][4] = {};

    for (int k0 = 0; k0 < K; k0 += 16) {
        #pragma unroll
        for (int r = 0; r < 4; r++) {
            int e  = tid + r * 256;
            int mm = e >> 4, kk = e & 15;
            As[kk][mm] = A[(size_t)(m0 + mm) * K + k0 + kk];
            Ws[kk][mm] = W[(size_t)(n0 + mm) * K + k0 + kk];
        }
        __syncthreads();
        #pragma unroll
        for (int kk = 0; kk < 16; kk++) {
            float4 a4 = *reinterpret_cast<const float4*>(&As[kk][ty * 4]);
            float4 b4 = *reinterpret_cast<const float4*>(&Ws[kk][tx * 4]);
            float a[4] = {a4.x, a4.y, a4.z, a4.w};
            float b[4] = {b4.x, b4.y, b4.z, b4.w};
            #pragma unroll
            for (int i = 0; i < 4; i++)
                #pragma unroll
                for (int j = 0; j < 4; j++)
                    acc[i][j] = fmaf(a[i], b[j], acc[i][j]);
        }
        __syncthreads();
    }

    float* out = which == 0 ? g_Q : which == 1 ? g_K : which == 2 ? g_V
               : which == 3 ? g_FK : g_FV;
    #pragma unroll
    for (int i = 0; i < 4; i++) {
        int m  = m0 + ty * 4 + i;
        int bb = m / Sx, s = m - bb * Sx;
        #pragma unroll
        for (int j = 0; j < 4; j++) {
            int n = n0 + tx * 4 + j;
            int h = n >> 6, d = n & 63;
            out[(((size_t)(bb * H_ + h)) * Sx + s) * D_ + d] = acc[i][j] + bias[n];
        }
    }
}

// ---------------- output GEMM + bias + residual: g_Y = g_CTX @ Wo^T + bo + hs --
__global__ void k_out(const float* __restrict__ W, const float* __restrict__ bias,
                      const float* __restrict__ res) {
    __shared__ float As[16][68];
    __shared__ float Ws[16][68];
    const int tid = threadIdx.x;
    const int tx = tid & 15, ty = tid >> 4;
    const int m0 = blockIdx.y * 64, n0 = blockIdx.x * 64;
    float acc[4][4] = {};
    const float* A = g_CTX;

    for (int k0 = 0; k0 < DM_; k0 += 16) {
        #pragma unroll
        for (int r = 0; r < 4; r++) {
            int e  = tid + r * 256;
            int mm = e >> 4, kk = e & 15;
            As[kk][mm] = A[(size_t)(m0 + mm) * DM_ + k0 + kk];
            Ws[kk][mm] = W[(size_t)(n0 + mm) * DM_ + k0 + kk];
        }
        __syncthreads();
        #pragma unroll
        for (int kk = 0; kk < 16; kk++) {
            float4 a4 = *reinterpret_cast<const float4*>(&As[kk][ty * 4]);
            float4 b4 = *reinterpret_cast<const float4*>(&Ws[kk][tx * 4]);
            float a[4] = {a4.x, a4.y, a4.z, a4.w};
            float b[4] = {b4.x, b4.y, b4.z, b4.w};
            #pragma unroll
            for (int i = 0; i < 4; i++)
                #pragma unroll
                for (int j = 0; j < 4; j++)
                    acc[i][j] = fmaf(a[i], b[j], acc[i][j]);
        }
        __syncthreads();
    }
    #pragma unroll
    for (int i = 0; i < 4; i++) {
        int m = m0 + ty * 4 + i;
        #pragma unroll
        for (int j = 0; j < 4; j++) {
            int n = n0 + tx * 4 + j;
            g_Y[(size_t)m * DM_ + n] = acc[i][j] + bias[n] + res[(size_t)m * DM_ + n];
        }
    }
}

// ---------------- fused attention: self (with rel-pos bias) + encoder branch ---
// grid (S/64, H, B), 256 threads. Thread = (row = tid>>2, part = tid&3).
// dyn smem: k_s[64][68] | v_s[64][68] | e_s[127][68] | p_s[64][68]
#define ATTN_SMEM_FLOATS (4352 + 4352 + 8636 + 4352)
#define ATTN_SMEM_BYTES  (ATTN_SMEM_FLOATS * 4)

__global__ void __launch_bounds__(256)
k_attn(const float* __restrict__ E, const float* __restrict__ mask) {
    extern __shared__ float sm[];
    float* k_s = sm;
    float* v_s = sm + 4352;
    float* e_s = sm + 8704;
    float* p_s = sm + 17340;

    const int tid  = threadIdx.x;
    const int row  = tid >> 2;
    const int part = tid & 3;
    const int l0   = blockIdx.x * 64;
    const int h    = blockIdx.y;
    const int b    = blockIdx.z;
    const size_t bh = (size_t)(b * H_ + h);
    const float inv_sqrt_d = 0.125f;

    // stage q tile through p_s (coalesced), then into registers
    {
        const float* Qp = g_Q + (bh * S_ + l0) * D_;
        for (int idx = tid; idx < 64 * 16; idx += 256) {
            int r = idx >> 4, d4 = idx & 15;
            *reinterpret_cast<float4*>(&p_s[r * 68 + d4 * 4]) =
                *reinterpret_cast<const float4*>(&Qp[(size_t)r * 64 + d4 * 4]);
        }
    }
    __syncthreads();
    float q[64];
    #pragma unroll
    for (int d4 = 0; d4 < 16; d4++) {
        float4 t = *reinterpret_cast<const float4*>(&p_s[row * 68 + d4 * 4]);
        q[d4 * 4 + 0] = t.x; q[d4 * 4 + 1] = t.y;
        q[d4 * 4 + 2] = t.z; q[d4 * 4 + 3] = t.w;
    }

    float acc[16], save[16];
    float mstate = -1e30f, ll = 0.f;
    #pragma unroll
    for (int i = 0; i < 16; i++) acc[i] = 0.f;

    // ================= self attention (with relative position bias) ============
    for (int t = 0; t < 16; t++) {
        const int r0 = t * 64;
        __syncthreads();
        {
            const float* Kp = g_K + (bh * S_ + r0) * D_;
            const float* Vp = g_V + (bh * S_ + r0) * D_;
            for (int idx = tid; idx < 64 * 16; idx += 256) {
                int r = idx >> 4, d4 = idx & 15;
                *reinterpret_cast<float4*>(&k_s[r * 68 + d4 * 4]) =
                    *reinterpret_cast<const float4*>(&Kp[(size_t)r * 64 + d4 * 4]);
                *reinterpret_cast<float4*>(&v_s[r * 68 + d4 * 4]) =
                    *reinterpret_cast<const float4*>(&Vp[(size_t)r * 64 + d4 * 4]);
            }
            // E window: j = l - r + 1023 -> rows [jbase, jbase+126], jbase in [0,1920]
            const int jbase = l0 - r0 + 960;
            const float* Ep = E + (size_t)jbase * 64;
            for (int idx = tid; idx < 127 * 16; idx += 256) {
                int r = idx >> 4, d4 = idx & 15;
                *reinterpret_cast<float4*>(&e_s[r * 68 + d4 * 4]) =
                    *reinterpret_cast<const float4*>(&Ep[(size_t)r * 64 + d4 * 4]);
            }
        }
        __syncthreads();

        // pass 1: raw scores -> p_s, track tile max.
        // score = ( q·k + (q+k)·E_j ) * inv_sqrt_d + mask
        float tmax = -1e30f;
        #pragma unroll
        for (int cc = 0; cc < 16; cc++) {
            int c = part + cc * 4;
            const float* kp = &k_s[c * 68];
            const float* ep = &e_s[(row - c + 63) * 68];
            float sv = 0.f, sb = 0.f;
            #pragma unroll
            for (int d = 0; d < 64; d += 4) {
                float4 k4 = *reinterpret_cast<const float4*>(kp + d);
                float4 e4 = *reinterpret_cast<const float4*>(ep + d);
                sv = fmaf(q[d + 0], k4.x, sv); sb = fmaf(q[d + 0] + k4.x, e4.x, sb);
                sv = fmaf(q[d + 1], k4.y, sv); sb = fmaf(q[d + 1] + k4.y, e4.y, sb);
                sv = fmaf(q[d + 2], k4.z, sv); sb = fmaf(q[d + 2] + k4.z, e4.z, sb);
                sv = fmaf(q[d + 3], k4.w, sv); sb = fmaf(q[d + 3] + k4.w, e4.w, sb);
            }
            float sc = (sv + sb) * inv_sqrt_d + mask[b * S_ + r0 + c];
            p_s[row * 68 + c] = sc;
            tmax = fmaxf(tmax, sc);
        }
        tmax = fmaxf(tmax, __shfl_xor_sync(0xffffffffu, tmax, 1));
        tmax = fmaxf(tmax, __shfl_xor_sync(0xffffffffu, tmax, 2));
        float m_new = fmaxf(mstate, tmax);
        float corr  = __expf(mstate - m_new);
        ll *= corr;
        #pragma unroll
        for (int i = 0; i < 16; i++) acc[i] *= corr;
        __syncwarp();
        float psum = 0.f;
        #pragma unroll
        for (int cc = 0; cc < 16; cc++) {
            int c = part + cc * 4;
            float p = __expf(p_s[row * 68 + c] - m_new);
            p_s[row * 68 + c] = p;
            psum += p;
        }
        psum += __shfl_xor_sync(0xffffffffu, psum, 1);
        psum += __shfl_xor_sync(0xffffffffu, psum, 2);
        ll += psum;
        mstate = m_new;
        __syncwarp();
        // PV: acc[d-slice] += p[c] * V[c][d-slice]
        #pragma unroll 4
        for (int c2 = 0; c2 < 64; c2++) {
            float pv = p_s[row * 68 + c2];
            const float* vp = &v_s[c2 * 68 + part * 16];
            #pragma unroll
            for (int i = 0; i < 16; i += 4) {
                float4 v4 = *reinterpret_cast<const float4*>(vp + i);
                acc[i + 0] = fmaf(pv, v4.x, acc[i + 0]);
                acc[i + 1] = fmaf(pv, v4.y, acc[i + 1]);
                acc[i + 2] = fmaf(pv, v4.z, acc[i + 2]);
                acc[i + 3] = fmaf(pv, v4.w, acc[i + 3]);
            }
        }
    }
    {
        float inv = 1.f / ll;
        #pragma unroll
        for (int i = 0; i < 16; i++) { save[i] = acc[i] * inv; acc[i] = 0.f; }
    }
    mstate = -1e30f; ll = 0.f;

    // ================= encoder cross attention (no bias, no mask) ==============
    for (int t = 0; t < 8; t++) {
        const int r0 = t * 64;
        __syncthreads();
        {
            const float* Kp = g_FK + (bh * SE_ + r0) * D_;
            const float* Vp = g_FV + (bh * SE_ + r0) * D_;
            for (int idx = tid; idx < 64 * 16; idx += 256) {
                int r = idx >> 4, d4 = idx & 15;
                *reinterpret_cast<float4*>(&k_s[r * 68 + d4 * 4]) =
                    *reinterpret_cast<const float4*>(&Kp[(size_t)r * 64 + d4 * 4]);
                *reinterpret_cast<float4*>(&v_s[r * 68 + d4 * 4]) =
                    *reinterpret_cast<const float4*>(&Vp[(size_t)r * 64 + d4 * 4]);
            }
        }
        __syncthreads();

        float tmax = -1e30f;
        #pragma unroll
        for (int cc = 0; cc < 16; cc++) {
            int c = part + cc * 4;
            const float* kp = &k_s[c * 68];
            float sv = 0.f;
            #pragma unroll
            for (int d = 0; d < 64; d += 4) {
                float4 k4 = *reinterpret_cast<const float4*>(kp + d);
                sv = fmaf(q[d + 0], k4.x, sv);
                sv = fmaf(q[d + 1], k4.y, sv);
                sv = fmaf(q[d + 2], k4.z, sv);
                sv = fmaf(q[d + 3], k4.w, sv);
            }
            float sc = sv * inv_sqrt_d;
            p_s[row * 68 + c] = sc;
            tmax = fmaxf(tmax, sc);
        }
        tmax = fmaxf(tmax, __shfl_xor_sync(0xffffffffu, tmax, 1));
        tmax = fmaxf(tmax, __shfl_xor_sync(0xffffffffu, tmax, 2));
        float m_new = fmaxf(mstate, tmax);
        float corr  = __expf(mstate - m_new);
        ll *= corr;
        #pragma unroll
        for (int i = 0; i < 16; i++) acc[i] *= corr;
        __syncwarp();
        float psum = 0.f;
        #pragma unroll
        for (int cc = 0; cc < 16; cc++) {
            int c = part + cc * 4;
            float p = __expf(p_s[row * 68 + c] - m_new);
            p_s[row * 68 + c] = p;
            psum += p;
        }
        psum += __shfl_xor_sync(0xffffffffu, psum, 1);
        psum += __shfl_xor_sync(0xffffffffu, psum, 2);
        ll += psum;
        mstate = m_new;
        __syncwarp();
        #pragma unroll 4
        for (int c2 = 0; c2 < 64; c2++) {
            float pv = p_s[row * 68 + c2];
            const float* vp = &v_s[c2 * 68 + part * 16];
            #pragma unroll
            for (int i = 0; i < 16; i += 4) {
                float4 v4 = *reinterpret_cast<const float4*>(vp + i);
                acc[i + 0] = fmaf(pv, v4.x, acc[i + 0]);
                acc[i + 1] = fmaf(pv, v4.y, acc[i + 1]);
                acc[i + 2] = fmaf(pv, v4.z, acc[i + 2]);
                acc[i + 3] = fmaf(pv, v4.w, acc[i + 3]);
            }
        }
    }

    // ctx = self_ctx + enc_ctx, merged-head layout [B,S,H*D]
    {
        float inv = 1.f / ll;
        float* cp = g_CTX + (((size_t)b * S_ + (l0 + row)) * H_ + h) * D_ + part * 16;
        #pragma unroll
        for (int i = 0; i < 16; i += 4) {
            float4 o;
            o.x = save[i + 0] + acc[i + 0] * inv;
            o.y = save[i + 1] + acc[i + 1] * inv;
            o.z = save[i + 2] + acc[i + 2] * inv;
            o.w = save[i + 3] + acc[i + 3] * inv;
            *reinterpret_cast<float4*>(cp + i) = o;
        }
    }
}

// ---------------- LayerNorm over last dim (row per block) ----------------------
__global__ void k_ln(const float* __restrict__ ga, const float* __restrict__ be,
                     float* __restrict__ out) {
    const int row = blockIdx.x;
    const int tid = threadIdx.x;
    const float* y = g_Y + (size_t)row * DM_;
    float4 t = *reinterpret_cast<const float4*>(y + tid * 4);
    float s  = t.x + t.y + t.z + t.w;
    float s2 = t.x * t.x + t.y * t.y + t.z * t.z + t.w * t.w;
    #pragma unroll
    for (int o = 16; o > 0; o >>= 1) {
        s  += __shfl_xor_sync(0xffffffffu, s,  o);
        s2 += __shfl_xor_sync(0xffffffffu, s2, o);
    }
    __shared__ float sh[16];
    int w = tid >> 5, lane = tid & 31;
    if (lane == 0) { sh[w] = s; sh[8 + w] = s2; }
    __syncthreads();
    if (tid == 0) {
        float S = 0.f, S2 = 0.f;
        #pragma unroll
        for (int i = 0; i < 8; i++) { S += sh[i]; S2 += sh[8 + i]; }
        sh[0] = S; sh[1] = S2;
    }
    __syncthreads();
    float mu  = sh[0] * (1.f / DM_);
    float var = sh[1] * (1.f / DM_) - mu * mu;
    float r   = rsqrtf(var + 1e-12f);
    int c = tid * 4;
    float4 gv = *reinterpret_cast<const float4*>(ga + c);
    float4 bv = *reinterpret_cast<const float4*>(be + c);
    float4 o;
    o.x = (t.x - mu) * r * gv.x + bv.x;
    o.y = (t.y - mu) * r * gv.y + bv.y;
    o.z = (t.z - mu) * r * gv.z + bv.z;
    o.w = (t.w - mu) * r * gv.w + bv.w;
    *reinterpret_cast<float4*>(out + (size_t)row * DM_ + c) = o;
}

// ---------------- launch --------------------------------------------------------
extern "C" void kernel_launch(void* const* d_in, const int* in_sizes, int n_in,
                              void* d_out, int out_size) {
    (void)in_sizes; (void)n_in; (void)out_size;
    const float* hs   = (const float*)d_in[0];
    const float* mask = (const float*)d_in[1];
    const float* enc  = (const float*)d_in[2];
    const float* Wq   = (const float*)d_in[3];
    const float* bq   = (const float*)d_in[4];
    const float* Wk   = (const float*)d_in[5];
    const float* bk   = (const float*)d_in[6];
    const float* Wv   = (const float*)d_in[7];
    const float* bv   = (const float*)d_in[8];
    const float* Wfk  = (const float*)d_in[9];
    const float* bfk  = (const float*)d_in[10];
    const float* Wfv  = (const float*)d_in[11];
    const float* bfv  = (const float*)d_in[12];
    const float* E    = (const float*)d_in[13];
    const float* Wo   = (const float*)d_in[14];
    const float* bo   = (const float*)d_in[15];
    const float* lg   = (const float*)d_in[16];
    const float* lb   = (const float*)d_in[17];
    float* out = (float*)d_out;

    dim3 blk(256);
    // QKV projections: M=4096, N=1024, K=1024
    k_proj<<<dim3(16, 64), blk>>>(hs, Wq, bq, 0, 1024, 1024);
    k_proj<<<dim3(16, 64), blk>>>(hs, Wk, bk, 1, 1024, 1024);
    k_proj<<<dim3(16, 64), blk>>>(hs, Wv, bv, 2, 1024, 1024);
    // encoder projections: M=2048, N=1024, K=512
    k_proj<<<dim3(16, 32), blk>>>(enc, Wfk, bfk, 3, 512, 512);
    k_proj<<<dim3(16, 32), blk>>>(enc, Wfv, bfv, 4, 512, 512);

    cudaFuncSetAttribute(k_attn, cudaFuncAttributeMaxDynamicSharedMemorySize,
                         ATTN_SMEM_BYTES);
    k_attn<<<dim3(16, 16, 4), blk, ATTN_SMEM_BYTES>>>(E, mask);

    k_out<<<dim3(16, 64), blk>>>(Wo, bo, hs);
    k_ln<<<4096, blk>>>(lg, lb, out);
}

// round 3
// speedup vs baseline: 1.2361x; 1.2361x over previous
#include <cuda_runtime.h>
#include <cuda_bf16.h>
#include <cstdint>

#define B_  4
#define S_  1024
#define DM_ 1024
#define H_  16
#define D_  64
#define SE_ 512
#define DF_ 512

// ===================== scratch (static device arrays) =====================
__device__ float g_Q [B_*H_*S_ *D_];
__device__ float g_K [B_*H_*S_ *D_];
__device__ float g_V [B_*H_*S_ *D_];
__device__ float g_FK[B_*H_*SE_*D_];
__device__ float g_FV[B_*H_*SE_*D_];
__device__ float g_Y  [B_*S_*DM_];

// split-bf16 operands
__device__ __align__(16) __nv_bfloat16 g_hs_hi [B_*S_*DM_];
__device__ __align__(16) __nv_bfloat16 g_hs_lo [B_*S_*DM_];
__device__ __align__(16) __nv_bfloat16 g_enc_hi[B_*SE_*DF_];
__device__ __align__(16) __nv_bfloat16 g_enc_lo[B_*SE_*DF_];
__device__ __align__(16) __nv_bfloat16 g_ctx_hi[B_*S_*DM_];
__device__ __align__(16) __nv_bfloat16 g_ctx_lo[B_*S_*DM_];
#define WOFF_Q  0
#define WOFF_K  1048576
#define WOFF_V  2097152
#define WOFF_O  3145728
#define WOFF_FK 4194304
#define WOFF_FV 4718592
__device__ __align__(16) __nv_bfloat16 g_wb_hi[5242880];
__device__ __align__(16) __nv_bfloat16 g_wb_lo[5242880];

// ===================== helpers =====================
__device__ __forceinline__ uint32_t smem_to_u32(const void* p) {
    uint32_t a;
    asm("{ .reg .u64 t; cvta.to.shared.u64 t, %1; cvt.u32.u64 %0, t; }" : "=r"(a) : "l"(p));
    return a;
}
__device__ __forceinline__ void cp_async16(uint32_t saddr, const void* gptr) {
    asm volatile("cp.async.cg.shared.global [%0], [%1], 16;" :: "r"(saddr), "l"(gptr));
}
__device__ __forceinline__ void ldsm_x4(uint32_t& r0, uint32_t& r1, uint32_t& r2,
                                        uint32_t& r3, uint32_t addr) {
    asm volatile("ldmatrix.sync.aligned.m8n8.x4.shared.b16 {%0,%1,%2,%3}, [%4];"
                 : "=r"(r0), "=r"(r1), "=r"(r2), "=r"(r3) : "r"(addr));
}
__device__ __forceinline__ void mma16816(float* c, const uint32_t* a,
                                         uint32_t b0, uint32_t b1) {
    asm volatile(
        "mma.sync.aligned.m16n8k16.row.col.f32.bf16.bf16.f32 "
        "{%0,%1,%2,%3}, {%4,%5,%6,%7}, {%8,%9}, {%0,%1,%2,%3};"
        : "+f"(c[0]), "+f"(c[1]), "+f"(c[2]), "+f"(c[3])
        : "r"(a[0]), "r"(a[1]), "r"(a[2]), "r"(a[3]), "r"(b0), "r"(b1));
}

// ===================== fp32 -> (hi,lo) bf16 split =====================
__global__ void k_cvt(const float* __restrict__ src, int which, int n4) {
    __nv_bfloat16 *hi, *lo;
    switch (which) {
        case 0: hi = g_hs_hi;           lo = g_hs_lo;           break;
        case 1: hi = g_enc_hi;          lo = g_enc_lo;          break;
        case 2: hi = g_wb_hi + WOFF_Q;  lo = g_wb_lo + WOFF_Q;  break;
        case 3: hi = g_wb_hi + WOFF_K;  lo = g_wb_lo + WOFF_K;  break;
        case 4: hi = g_wb_hi + WOFF_V;  lo = g_wb_lo + WOFF_V;  break;
        case 5: hi = g_wb_hi + WOFF_O;  lo = g_wb_lo + WOFF_O;  break;
        case 6: hi = g_wb_hi + WOFF_FK; lo = g_wb_lo + WOFF_FK; break;
        default:hi = g_wb_hi + WOFF_FV; lo = g_wb_lo + WOFF_FV; break;
    }
    int i = blockIdx.x * 256 + threadIdx.x;
    if (i >= n4) return;
    float4 v = reinterpret_cast<const float4*>(src)[i];
    __nv_bfloat16 hx = __float2bfloat16_rn(v.x);
    __nv_bfloat16 hy = __float2bfloat16_rn(v.y);
    __nv_bfloat16 hz = __float2bfloat16_rn(v.z);
    __nv_bfloat16 hw = __float2bfloat16_rn(v.w);
    __nv_bfloat16 lx = __float2bfloat16_rn(v.x - __bfloat162float(hx));
    __nv_bfloat16 ly = __float2bfloat16_rn(v.y - __bfloat162float(hy));
    __nv_bfloat16 lz = __float2bfloat16_rn(v.z - __bfloat162float(hz));
    __nv_bfloat16 lw = __float2bfloat16_rn(v.w - __bfloat162float(hw));
    __nv_bfloat162* h2 = reinterpret_cast<__nv_bfloat162*>(hi);
    __nv_bfloat162* l2 = reinterpret_cast<__nv_bfloat162*>(lo);
    h2[2*i]   = __halves2bfloat162(hx, hy);
    h2[2*i+1] = __halves2bfloat162(hz, hw);
    l2[2*i]   = __halves2bfloat162(lx, ly);
    l2[2*i+1] = __halves2bfloat162(lz, lw);
}

// ===================== mma.sync split-bf16 GEMM =====================
// C[M,1024] = A[M,K] @ W[1024,K]^T. CTA tile 128x128, K-chunk 32, 8 warps.
// smem stage: Ahi[128][40] | Alo | Whi[128][40] | Wlo  (40960 B), double buffered.
#define GSTAGE 40960
#define GEMM_SMEM_BYTES (2*GSTAGE)

__global__ void __launch_bounds__(256) k_gemm(const float* __restrict__ bias,
                                              const float* __restrict__ res,
                                              int which) {
    extern __shared__ char dsm[];
    const uint32_t sbase = smem_to_u32(dsm);
    const int tid = threadIdx.x;
    const int lane = tid & 31, wid = tid >> 5;
    const int warp_m = wid & 1, warp_n = wid >> 1;
    const int m0 = blockIdx.y * 128, n0 = blockIdx.x * 128;

    const __nv_bfloat16 *Ahi, *Alo, *Whi, *Wlo;
    float* dst;
    int K, Sx;
    switch (which) {
        case 0: Ahi=g_hs_hi;  Alo=g_hs_lo;  Whi=g_wb_hi+WOFF_Q;  Wlo=g_wb_lo+WOFF_Q;  dst=g_Q;  K=1024; Sx=1024; break;
        case 1: Ahi=g_hs_hi;  Alo=g_hs_lo;  Whi=g_wb_hi+WOFF_K;  Wlo=g_wb_lo+WOFF_K;  dst=g_K;  K=1024; Sx=1024; break;
        case 2: Ahi=g_hs_hi;  Alo=g_hs_lo;  Whi=g_wb_hi+WOFF_V;  Wlo=g_wb_lo+WOFF_V;  dst=g_V;  K=1024; Sx=1024; break;
        case 3: Ahi=g_enc_hi; Alo=g_enc_lo; Whi=g_wb_hi+WOFF_FK; Wlo=g_wb_lo+WOFF_FK; dst=g_FK; K=512;  Sx=512;  break;
        case 4: Ahi=g_enc_hi; Alo=g_enc_lo; Whi=g_wb_hi+WOFF_FV; Wlo=g_wb_lo+WOFF_FV; dst=g_FV; K=512;  Sx=512;  break;
        default:Ahi=g_ctx_hi; Alo=g_ctx_lo; Whi=g_wb_hi+WOFF_O;  Wlo=g_wb_lo+WOFF_O;  dst=g_Y;  K=1024; Sx=1024; break;
    }
    const int nk = K >> 5;

    // ldmatrix per-thread offsets
    const int sub = lane >> 3, lr = lane & 7;
    const int a_row = (sub & 1) * 8 + lr, a_colB = (sub >> 1) * 16;   // bytes
    const int b_row = (sub >> 1) * 8 + lr, b_colB = (sub & 1) * 16;

    float acc[4][4][4] = {};

    // cp.async producer for chunk c
    auto cp_chunk = [&](int c) {
        const int s = c & 1;
        const uint32_t st = sbase + s * GSTAGE;
        const int k0 = c * 32;
        #pragma unroll
        for (int i = 0; i < 2; i++) {
            int u = tid + i * 256;               // 0..511
            int r = u >> 2, cg = u & 3;
            uint32_t so = (uint32_t)(r * 80 + cg * 16);
            size_t ga = (size_t)(m0 + r) * K + k0 + cg * 8;
            size_t gw = (size_t)(n0 + r) * K + k0 + cg * 8;
            cp_async16(st + so,         Ahi + ga);
            cp_async16(st + 10240 + so, Alo + ga);
            cp_async16(st + 20480 + so, Whi + gw);
            cp_async16(st + 30720 + so, Wlo + gw);
        }
        asm volatile("cp.async.commit_group;" ::: "memory");
    };

    cp_chunk(0);
    for (int c = 0; c < nk; c++) {
        if (c + 1 < nk) {
            cp_chunk(c + 1);
            asm volatile("cp.async.wait_group 1;" ::: "memory");
        } else {
            asm volatile("cp.async.wait_group 0;" ::: "memory");
        }
        __syncthreads();
        const uint32_t st = sbase + (c & 1) * GSTAGE;
        #pragma unroll
        for (int ks = 0; ks < 2; ks++) {
            uint32_t bh[8], bl[8];
            #pragma unroll
            for (int np = 0; np < 2; np++) {
                uint32_t baddr = st + 20480 +
                    (uint32_t)((warp_n * 32 + np * 16 + b_row) * 80 + ks * 32 + b_colB);
                ldsm_x4(bh[np*4+0], bh[np*4+1], bh[np*4+2], bh[np*4+3], baddr);
                ldsm_x4(bl[np*4+0], bl[np*4+1], bl[np*4+2], bl[np*4+3], baddr + 10240);
            }
            #pragma unroll
            for (int mf = 0; mf < 4; mf++) {
                uint32_t ah[4], al[4];
                uint32_t aaddr = st +
                    (uint32_t)((warp_m * 64 + mf * 16 + a_row) * 80 + ks * 32 + a_colB);
                ldsm_x4(ah[0], ah[1], ah[2], ah[3], aaddr);
                ldsm_x4(al[0], al[1], al[2], al[3], aaddr + 10240);
                #pragma unroll
                for (int nf = 0; nf < 4; nf++) {
                    const int np = nf >> 1, q = nf & 1;
                    uint32_t b0h = bh[np*4 + q*2], b1h = bh[np*4 + q*2 + 1];
                    uint32_t b0l = bl[np*4 + q*2], b1l = bl[np*4 + q*2 + 1];
                    mma16816(acc[mf][nf], ah, b0h, b1h);
                    mma16816(acc[mf][nf], ah, b0l, b1l);
                    mma16816(acc[mf][nf], al, b0h, b1h);
                }
            }
        }
        __syncthreads();
    }

    // epilogue
    const int gID = lane >> 2, tc2 = (lane & 3) * 2;
    #pragma unroll
    for (int mf = 0; mf < 4; mf++) {
        #pragma unroll
        for (int nf = 0; nf < 4; nf++) {
            int n = n0 + warp_n * 32 + nf * 8 + tc2;
            float b0 = bias[n], b1 = bias[n + 1];
            #pragma unroll
            for (int half = 0; half < 2; half++) {
                int m = m0 + warp_m * 64 + mf * 16 + gID + half * 8;
                float v0 = acc[mf][nf][half*2 + 0] + b0;
                float v1 = acc[mf][nf][half*2 + 1] + b1;
                if (which < 5) {
                    int bb = m / Sx, srow = m - bb * Sx;
                    int h = n >> 6, d = n & 63;
                    float2 o = {v0, v1};
                    *reinterpret_cast<float2*>(
                        dst + (((size_t)(bb * H_ + h)) * Sx + srow) * 64 + d) = o;
                } else {
                    const float2 r2 = *reinterpret_cast<const float2*>(
                        res + (size_t)m * DM_ + n);
                    float2 o = {v0 + r2.x, v1 + r2.y};
                    *reinterpret_cast<float2*>(dst + (size_t)m * DM_ + n) = o;
                }
            }
        }
    }
}

// ---------------- fused attention: self (with rel-pos bias) + encoder branch ---
// grid (S/64, H, B), 256 threads. Thread = (row = tid>>2, part = tid&3).
#define ATTN_SMEM_FLOATS (4352 + 4352 + 8636 + 4352)
#define ATTN_SMEM_BYTES  (ATTN_SMEM_FLOATS * 4)

__global__ void __launch_bounds__(256)
k_attn(const float* __restrict__ E, const float* __restrict__ mask) {
    extern __shared__ float sm[];
    float* k_s = sm;
    float* v_s = sm + 4352;
    float* e_s = sm + 8704;
    float* p_s = sm + 17340;

    const int tid  = threadIdx.x;
    const int row  = tid >> 2;
    const int part = tid & 3;
    const int l0   = blockIdx.x * 64;
    const int h    = blockIdx.y;
    const int b    = blockIdx.z;
    const size_t bh = (size_t)(b * H_ + h);
    const float inv_sqrt_d = 0.125f;

    {
        const float* Qp = g_Q + (bh * S_ + l0) * D_;
        for (int idx = tid; idx < 64 * 16; idx += 256) {
            int r = idx >> 4, d4 = idx & 15;
            *reinterpret_cast<float4*>(&p_s[r * 68 + d4 * 4]) =
                *reinterpret_cast<const float4*>(&Qp[(size_t)r * 64 + d4 * 4]);
        }
    }
    __syncthreads();
    float q[64];
    #pragma unroll
    for (int d4 = 0; d4 < 16; d4++) {
        float4 t = *reinterpret_cast<const float4*>(&p_s[row * 68 + d4 * 4]);
        q[d4 * 4 + 0] = t.x; q[d4 * 4 + 1] = t.y;
        q[d4 * 4 + 2] = t.z; q[d4 * 4 + 3] = t.w;
    }

    float acc[16], save[16];
    float mstate = -1e30f, ll = 0.f;
    #pragma unroll
    for (int i = 0; i < 16; i++) acc[i] = 0.f;

    for (int t = 0; t < 16; t++) {
        const int r0 = t * 64;
        __syncthreads();
        {
            const float* Kp = g_K + (bh * S_ + r0) * D_;
            const float* Vp = g_V + (bh * S_ + r0) * D_;
            for (int idx = tid; idx < 64 * 16; idx += 256) {
                int r = idx >> 4, d4 = idx & 15;
                *reinterpret_cast<float4*>(&k_s[r * 68 + d4 * 4]) =
                    *reinterpret_cast<const float4*>(&Kp[(size_t)r * 64 + d4 * 4]);
                *reinterpret_cast<float4*>(&v_s[r * 68 + d4 * 4]) =
                    *reinterpret_cast<const float4*>(&Vp[(size_t)r * 64 + d4 * 4]);
            }
            const int jbase = l0 - r0 + 960;
            const float* Ep = E + (size_t)jbase * 64;
            for (int idx = tid; idx < 127 * 16; idx += 256) {
                int r = idx >> 4, d4 = idx & 15;
                *reinterpret_cast<float4*>(&e_s[r * 68 + d4 * 4]) =
                    *reinterpret_cast<const float4*>(&Ep[(size_t)r * 64 + d4 * 4]);
            }
        }
        __syncthreads();

        float tmax = -1e30f;
        #pragma unroll
        for (int cc = 0; cc < 16; cc++) {
            int c = part + cc * 4;
            const float* kp = &k_s[c * 68];
            const float* ep = &e_s[(row - c + 63) * 68];
            float sv = 0.f, sb = 0.f;
            #pragma unroll
            for (int d = 0; d < 64; d += 4) {
                float4 k4 = *reinterpret_cast<const float4*>(kp + d);
                float4 e4 = *reinterpret_cast<const float4*>(ep + d);
                sv = fmaf(q[d + 0], k4.x, sv); sb = fmaf(q[d + 0] + k4.x, e4.x, sb);
                sv = fmaf(q[d + 1], k4.y, sv); sb = fmaf(q[d + 1] + k4.y, e4.y, sb);
                sv = fmaf(q[d + 2], k4.z, sv); sb = fmaf(q[d + 2] + k4.z, e4.z, sb);
                sv = fmaf(q[d + 3], k4.w, sv); sb = fmaf(q[d + 3] + k4.w, e4.w, sb);
            }
            float sc = (sv + sb) * inv_sqrt_d + mask[b * S_ + r0 + c];
            p_s[row * 68 + c] = sc;
            tmax = fmaxf(tmax, sc);
        }
        tmax = fmaxf(tmax, __shfl_xor_sync(0xffffffffu, tmax, 1));
        tmax = fmaxf(tmax, __shfl_xor_sync(0xffffffffu, tmax, 2));
        float m_new = fmaxf(mstate, tmax);
        float corr  = __expf(mstate - m_new);
        ll *= corr;
        #pragma unroll
        for (int i = 0; i < 16; i++) acc[i] *= corr;
        __syncwarp();
        float psum = 0.f;
        #pragma unroll
        for (int cc = 0; cc < 16; cc++) {
            int c = part + cc * 4;
            float p = __expf(p_s[row * 68 + c] - m_new);
            p_s[row * 68 + c] = p;
            psum += p;
        }
        psum += __shfl_xor_sync(0xffffffffu, psum, 1);
        psum += __shfl_xor_sync(0xffffffffu, psum, 2);
        ll += psum;
        mstate = m_new;
        __syncwarp();
        #pragma unroll 4
        for (int c2 = 0; c2 < 64; c2++) {
            float pv = p_s[row * 68 + c2];
            const float* vp = &v_s[c2 * 68 + part * 16];
            #pragma unroll
            for (int i = 0; i < 16; i += 4) {
                float4 v4 = *reinterpret_cast<const float4*>(vp + i);
                acc[i + 0] = fmaf(pv, v4.x, acc[i + 0]);
                acc[i + 1] = fmaf(pv, v4.y, acc[i + 1]);
                acc[i + 2] = fmaf(pv, v4.z, acc[i + 2]);
                acc[i + 3] = fmaf(pv, v4.w, acc[i + 3]);
            }
        }
    }
    {
        float inv = 1.f / ll;
        #pragma unroll
        for (int i = 0; i < 16; i++) { save[i] = acc[i] * inv; acc[i] = 0.f; }
    }
    mstate = -1e30f; ll = 0.f;

    for (int t = 0; t < 8; t++) {
        const int r0 = t * 64;
        __syncthreads();
        {
            const float* Kp = g_FK + (bh * SE_ + r0) * D_;
            const float* Vp = g_FV + (bh * SE_ + r0) * D_;
            for (int idx = tid; idx < 64 * 16; idx += 256) {
                int r = idx >> 4, d4 = idx & 15;
                *reinterpret_cast<float4*>(&k_s[r * 68 + d4 * 4]) =
                    *reinterpret_cast<const float4*>(&Kp[(size_t)r * 64 + d4 * 4]);
                *reinterpret_cast<float4*>(&v_s[r * 68 + d4 * 4]) =
                    *reinterpret_cast<const float4*>(&Vp[(size_t)r * 64 + d4 * 4]);
            }
        }
        __syncthreads();

        float tmax = -1e30f;
        #pragma unroll
        for (int cc = 0; cc < 16; cc++) {
            int c = part + cc * 4;
            const float* kp = &k_s[c * 68];
            float sv = 0.f;
            #pragma unroll
            for (int d = 0; d < 64; d += 4) {
                float4 k4 = *reinterpret_cast<const float4*>(kp + d);
                sv = fmaf(q[d + 0], k4.x, sv);
                sv = fmaf(q[d + 1], k4.y, sv);
                sv = fmaf(q[d + 2], k4.z, sv);
                sv = fmaf(q[d + 3], k4.w, sv);
            }
            float sc = sv * inv_sqrt_d;
            p_s[row * 68 + c] = sc;
            tmax = fmaxf(tmax, sc);
        }
        tmax = fmaxf(tmax, __shfl_xor_sync(0xffffffffu, tmax, 1));
        tmax = fmaxf(tmax, __shfl_xor_sync(0xffffffffu, tmax, 2));
        float m_new = fmaxf(mstate, tmax);
        float corr  = __expf(mstate - m_new);
        ll *= corr;
        #pragma unroll
        for (int i = 0; i < 16; i++) acc[i] *= corr;
        __syncwarp();
        float psum = 0.f;
        #pragma unroll
        for (int cc = 0; cc < 16; cc++) {
            int c = part + cc * 4;
            float p = __expf(p_s[row * 68 + c] - m_new);
            p_s[row * 68 + c] = p;
            psum += p;
        }
        psum += __shfl_xor_sync(0xffffffffu, psum, 1);
        psum += __shfl_xor_sync(0xffffffffu, psum, 2);
        ll += psum;
        mstate = m_new;
        __syncwarp();
        #pragma unroll 4
        for (int c2 = 0; c2 < 64; c2++) {
            float pv = p_s[row * 68 + c2];
            const float* vp = &v_s[c2 * 68 + part * 16];
            #pragma unroll
            for (int i = 0; i < 16; i += 4) {
                float4 v4 = *reinterpret_cast<const float4*>(vp + i);
                acc[i + 0] = fmaf(pv, v4.x, acc[i + 0]);
                acc[i + 1] = fmaf(pv, v4.y, acc[i + 1]);
                acc[i + 2] = fmaf(pv, v4.z, acc[i + 2]);
                acc[i + 3] = fmaf(pv, v4.w, acc[i + 3]);
            }
        }
    }

    // ctx = self_ctx + enc_ctx -> split bf16, merged-head layout [B,S,H*D]
    {
        float inv = 1.f / ll;
        size_t base = (((size_t)b * S_ + (l0 + row)) * H_ + h) * D_ + part * 16;
        __nv_bfloat16 hbuf[16], lbuf[16];
        #pragma unroll
        for (int i = 0; i < 16; i++) {
            float o = save[i] + acc[i] * inv;
            __nv_bfloat16 hi = __float2bfloat16_rn(o);
            hbuf[i] = hi;
            lbuf[i] = __float2bfloat16_rn(o - __bfloat162float(hi));
        }
        *reinterpret_cast<uint4*>(g_ctx_hi + base)     = *reinterpret_cast<uint4*>(hbuf);
        *reinterpret_cast<uint4*>(g_ctx_hi + base + 8) = *reinterpret_cast<uint4*>(hbuf + 8);
        *reinterpret_cast<uint4*>(g_ctx_lo + base)     = *reinterpret_cast<uint4*>(lbuf);
        *reinterpret_cast<uint4*>(g_ctx_lo + base + 8) = *reinterpret_cast<uint4*>(lbuf + 8);
    }
}

// ---------------- LayerNorm over last dim ----------------------
__global__ void k_ln(const float* __restrict__ ga, const float* __restrict__ be,
                     float* __restrict__ out) {
    const int row = blockIdx.x;
    const int tid = threadIdx.x;
    const float* y = g_Y + (size_t)row * DM_;
    float4 t = *reinterpret_cast<const float4*>(y + tid * 4);
    float s  = t.x + t.y + t.z + t.w;
    float s2 = t.x * t.x + t.y * t.y + t.z * t.z + t.w * t.w;
    #pragma unroll
    for (int o = 16; o > 0; o >>= 1) {
        s  += __shfl_xor_sync(0xffffffffu, s,  o);
        s2 += __shfl_xor_sync(0xffffffffu, s2, o);
    }
    __shared__ float sh[16];
    int w = tid >> 5, lane = tid & 31;
    if (lane == 0) { sh[w] = s; sh[8 + w] = s2; }
    __syncthreads();
    if (tid == 0) {
        float S = 0.f, S2 = 0.f;
        #pragma unroll
        for (int i = 0; i < 8; i++) { S += sh[i]; S2 += sh[8 + i]; }
        sh[0] = S; sh[1] = S2;
    }
    __syncthreads();
    float mu  = sh[0] * (1.f / DM_);
    float var = sh[1] * (1.f / DM_) - mu * mu;
    float r   = rsqrtf(var + 1e-12f);
    int c = tid * 4;
    float4 gv = *reinterpret_cast<const float4*>(ga + c);
    float4 bv = *reinterpret_cast<const float4*>(be + c);
    float4 o;
    o.x = (t.x - mu) * r * gv.x + bv.x;
    o.y = (t.y - mu) * r * gv.y + bv.y;
    o.z = (t.z - mu) * r * gv.z + bv.z;
    o.w = (t.w - mu) * r * gv.w + bv.w;
    *reinterpret_cast<float4*>(out + (size_t)row * DM_ + c) = o;
}

// ---------------- launch --------------------------------------------------------
extern "C" void kernel_launch(void* const* d_in, const int* in_sizes, int n_in,
                              void* d_out, int out_size) {
    (void)in_sizes; (void)n_in; (void)out_size;
    const float* hs   = (const float*)d_in[0];
    const float* mask = (const float*)d_in[1];
    const float* enc  = (const float*)d_in[2];
    const float* Wq   = (const float*)d_in[3];
    const float* bq   = (const float*)d_in[4];
    const float* Wk   = (const float*)d_in[5];
    const float* bk   = (const float*)d_in[6];
    const float* Wv   = (const float*)d_in[7];
    const float* bv   = (const float*)d_in[8];
    const float* Wfk  = (const float*)d_in[9];
    const float* bfk  = (const float*)d_in[10];
    const float* Wfv  = (const float*)d_in[11];
    const float* bfv  = (const float*)d_in[12];
    const float* E    = (const float*)d_in[13];
    const float* Wo   = (const float*)d_in[14];
    const float* bo   = (const float*)d_in[15];
    const float* lg   = (const float*)d_in[16];
    const float* lb   = (const float*)d_in[17];
    float* out = (float*)d_out;

    static bool attr_set = false;
    if (!attr_set) {
        cudaFuncSetAttribute(k_attn, cudaFuncAttributeMaxDynamicSharedMemorySize, ATTN_SMEM_BYTES);
        cudaFuncSetAttribute(k_gemm, cudaFuncAttributeMaxDynamicSharedMemorySize, GEMM_SMEM_BYTES);
        attr_set = true;
    }

    // fp32 -> split bf16 conversions
    k_cvt<<<4096, 256>>>(hs,  0, B_*S_*DM_/4);
    k_cvt<<<1024, 256>>>(enc, 1, B_*SE_*DF_/4);
    k_cvt<<<1024, 256>>>(Wq,  2, 1048576/4);
    k_cvt<<<1024, 256>>>(Wk,  3, 1048576/4);
    k_cvt<<<1024, 256>>>(Wv,  4, 1048576/4);
    k_cvt<<<1024, 256>>>(Wo,  5, 1048576/4);
    k_cvt<<< 512, 256>>>(Wfk, 6, 524288/4);
    k_cvt<<< 512, 256>>>(Wfv, 7, 524288/4);

    // tensor-core projections (tile 128x128)
    k_gemm<<<dim3(8, 32), 256, GEMM_SMEM_BYTES>>>(bq,  nullptr, 0);
    k_gemm<<<dim3(8, 32), 256, GEMM_SMEM_BYTES>>>(bk,  nullptr, 1);
    k_gemm<<<dim3(8, 32), 256, GEMM_SMEM_BYTES>>>(bv,  nullptr, 2);
    k_gemm<<<dim3(8, 16), 256, GEMM_SMEM_BYTES>>>(bfk, nullptr, 3);
    k_gemm<<<dim3(8, 16), 256, GEMM_SMEM_BYTES>>>(bfv, nullptr, 4);

    k_attn<<<dim3(16, 16, 4), 256, ATTN_SMEM_BYTES>>>(E, mask);

    k_gemm<<<dim3(8, 32), 256, GEMM_SMEM_BYTES>>>(bo, hs, 5);   // out proj + residual
    k_ln<<<4096, 256>>>(lg, lb, out);
}

// round 4
// speedup vs baseline: 4.4432x; 3.5944x over previous
#include <cuda_runtime.h>
#include <cuda_bf16.h>
#include <cstdint>

#define B_  4
#define S_  1024
#define DM_ 1024
#define H_  16
#define D_  64
#define SE_ 512
#define DF_ 512

typedef __nv_bfloat16 bf16;
typedef __nv_bfloat162 bf162;

// ===================== scratch =====================
__device__ float g_Y[B_*S_*DM_];

__device__ __align__(16) bf16 g_Qh [B_*H_*S_ *D_];
__device__ __align__(16) bf16 g_Ql [B_*H_*S_ *D_];
__device__ __align__(16) bf16 g_Kh [B_*H_*S_ *D_];
__device__ __align__(16) bf16 g_Kl [B_*H_*S_ *D_];
__device__ __align__(16) bf16 g_Vh [B_*H_*S_ *D_];
__device__ __align__(16) bf16 g_Vl [B_*H_*S_ *D_];
__device__ __align__(16) bf16 g_FKh[B_*H_*SE_*D_];
__device__ __align__(16) bf16 g_FKl[B_*H_*SE_*D_];
__device__ __align__(16) bf16 g_FVh[B_*H_*SE_*D_];
__device__ __align__(16) bf16 g_FVl[B_*H_*SE_*D_];
__device__ __align__(16) bf16 g_Eh [2047*64];
__device__ __align__(16) bf16 g_El [2047*64];

__device__ __align__(16) bf16 g_hs_hi [B_*S_*DM_];
__device__ __align__(16) bf16 g_hs_lo [B_*S_*DM_];
__device__ __align__(16) bf16 g_enc_hi[B_*SE_*DF_];
__device__ __align__(16) bf16 g_enc_lo[B_*SE_*DF_];
__device__ __align__(16) bf16 g_ctx_hi[B_*S_*DM_];
__device__ __align__(16) bf16 g_ctx_lo[B_*S_*DM_];
#define WOFF_Q  0
#define WOFF_K  1048576
#define WOFF_V  2097152
#define WOFF_O  3145728
#define WOFF_FK 4194304
#define WOFF_FV 4718592
__device__ __align__(16) bf16 g_wb_hi[5242880];
__device__ __align__(16) bf16 g_wb_lo[5242880];

// ===================== helpers =====================
__device__ __forceinline__ uint32_t smem_to_u32(const void* p) {
    uint32_t a;
    asm("{ .reg .u64 t; cvta.to.shared.u64 t, %1; cvt.u32.u64 %0, t; }" : "=r"(a) : "l"(p));
    return a;
}
__device__ __forceinline__ void cp_async16(uint32_t saddr, const void* gptr) {
    asm volatile("cp.async.cg.shared.global [%0], [%1], 16;" :: "r"(saddr), "l"(gptr));
}
#define CP_COMMIT() asm volatile("cp.async.commit_group;" ::: "memory")
#define CP_WAIT0()  asm volatile("cp.async.wait_group 0;" ::: "memory")
#define CP_WAIT1()  asm volatile("cp.async.wait_group 1;" ::: "memory")
__device__ __forceinline__ void ldsm_x4(uint32_t& r0, uint32_t& r1, uint32_t& r2,
                                        uint32_t& r3, uint32_t addr) {
    asm volatile("ldmatrix.sync.aligned.m8n8.x4.shared.b16 {%0,%1,%2,%3}, [%4];"
                 : "=r"(r0), "=r"(r1), "=r"(r2), "=r"(r3) : "r"(addr));
}
__device__ __forceinline__ void ldsm_x4_t(uint32_t& r0, uint32_t& r1, uint32_t& r2,
                                          uint32_t& r3, uint32_t addr) {
    asm volatile("ldmatrix.sync.aligned.m8n8.x4.trans.shared.b16 {%0,%1,%2,%3}, [%4];"
                 : "=r"(r0), "=r"(r1), "=r"(r2), "=r"(r3) : "r"(addr));
}
__device__ __forceinline__ void mma16816(float* c, const uint32_t* a,
                                         uint32_t b0, uint32_t b1) {
    asm volatile(
        "mma.sync.aligned.m16n8k16.row.col.f32.bf16.bf16.f32 "
        "{%0,%1,%2,%3}, {%4,%5,%6,%7}, {%8,%9}, {%0,%1,%2,%3};"
        : "+f"(c[0]), "+f"(c[1]), "+f"(c[2]), "+f"(c[3])
        : "r"(a[0]), "r"(a[1]), "r"(a[2]), "r"(a[3]), "r"(b0), "r"(b1));
}
__device__ __forceinline__ uint32_t pack2bf(float lo, float hi) {
    bf162 v = __floats2bfloat162_rn(lo, hi);
    return *reinterpret_cast<uint32_t*>(&v);
}

// ===================== fp32 -> (hi,lo) bf16 split =====================
__global__ void k_cvt(const float* __restrict__ src, int which, int n4) {
    bf16 *hi, *lo;
    switch (which) {
        case 0: hi = g_hs_hi;           lo = g_hs_lo;           break;
        case 1: hi = g_enc_hi;          lo = g_enc_lo;          break;
        case 2: hi = g_wb_hi + WOFF_Q;  lo = g_wb_lo + WOFF_Q;  break;
        case 3: hi = g_wb_hi + WOFF_K;  lo = g_wb_lo + WOFF_K;  break;
        case 4: hi = g_wb_hi + WOFF_V;  lo = g_wb_lo + WOFF_V;  break;
        case 5: hi = g_wb_hi + WOFF_O;  lo = g_wb_lo + WOFF_O;  break;
        case 6: hi = g_wb_hi + WOFF_FK; lo = g_wb_lo + WOFF_FK; break;
        case 7: hi = g_wb_hi + WOFF_FV; lo = g_wb_lo + WOFF_FV; break;
        default: hi = g_Eh; lo = g_El; break;
    }
    int i = blockIdx.x * 256 + threadIdx.x;
    if (i >= n4) return;
    float4 v = reinterpret_cast<const float4*>(src)[i];
    bf16 hx = __float2bfloat16_rn(v.x);
    bf16 hy = __float2bfloat16_rn(v.y);
    bf16 hz = __float2bfloat16_rn(v.z);
    bf16 hw = __float2bfloat16_rn(v.w);
    bf16 lx = __float2bfloat16_rn(v.x - __bfloat162float(hx));
    bf16 ly = __float2bfloat16_rn(v.y - __bfloat162float(hy));
    bf16 lz = __float2bfloat16_rn(v.z - __bfloat162float(hz));
    bf16 lw = __float2bfloat16_rn(v.w - __bfloat162float(hw));
    bf162* h2 = reinterpret_cast<bf162*>(hi);
    bf162* l2 = reinterpret_cast<bf162*>(lo);
    h2[2*i]   = __halves2bfloat162(hx, hy);
    h2[2*i+1] = __halves2bfloat162(hz, hw);
    l2[2*i]   = __halves2bfloat162(lx, ly);
    l2[2*i+1] = __halves2bfloat162(lz, lw);
}

// ===================== mma.sync split-bf16 GEMM =====================
#define GSTAGE 40960
#define GEMM_SMEM_BYTES (2*GSTAGE)

__global__ void __launch_bounds__(256) k_gemm(const float* __restrict__ bias,
                                              const float* __restrict__ res,
                                              int which) {
    extern __shared__ char dsm[];
    const uint32_t sbase = smem_to_u32(dsm);
    const int tid = threadIdx.x;
    const int lane = tid & 31, wid = tid >> 5;
    const int warp_m = wid & 1, warp_n = wid >> 1;
    const int m0 = blockIdx.y * 128, n0 = blockIdx.x * 128;

    const bf16 *Ahi, *Alo, *Whi, *Wlo;
    bf16 *dh = nullptr, *dl = nullptr;
    int K, Sx;
    switch (which) {
        case 0: Ahi=g_hs_hi;  Alo=g_hs_lo;  Whi=g_wb_hi+WOFF_Q;  Wlo=g_wb_lo+WOFF_Q;  dh=g_Qh;  dl=g_Ql;  K=1024; Sx=1024; break;
        case 1: Ahi=g_hs_hi;  Alo=g_hs_lo;  Whi=g_wb_hi+WOFF_K;  Wlo=g_wb_lo+WOFF_K;  dh=g_Kh;  dl=g_Kl;  K=1024; Sx=1024; break;
        case 2: Ahi=g_hs_hi;  Alo=g_hs_lo;  Whi=g_wb_hi+WOFF_V;  Wlo=g_wb_lo+WOFF_V;  dh=g_Vh;  dl=g_Vl;  K=1024; Sx=1024; break;
        case 3: Ahi=g_enc_hi; Alo=g_enc_lo; Whi=g_wb_hi+WOFF_FK; Wlo=g_wb_lo+WOFF_FK; dh=g_FKh; dl=g_FKl; K=512;  Sx=512;  break;
        case 4: Ahi=g_enc_hi; Alo=g_enc_lo; Whi=g_wb_hi+WOFF_FV; Wlo=g_wb_lo+WOFF_FV; dh=g_FVh; dl=g_FVl; K=512;  Sx=512;  break;
        default:Ahi=g_ctx_hi; Alo=g_ctx_lo; Whi=g_wb_hi+WOFF_O;  Wlo=g_wb_lo+WOFF_O;  K=1024; Sx=1024; break;
    }
    const int nk = K >> 5;

    const int sub = lane >> 3, lr = lane & 7;
    const int a_row = (sub & 1) * 8 + lr, a_colB = (sub >> 1) * 16;
    const int b_row = (sub >> 1) * 8 + lr, b_colB = (sub & 1) * 16;

    float acc[4][4][4] = {};

    auto cp_chunk = [&](int c) {
        const int s = c & 1;
        const uint32_t st = sbase + s * GSTAGE;
        const int k0 = c * 32;
        #pragma unroll
        for (int i = 0; i < 2; i++) {
            int u = tid + i * 256;
            int r = u >> 2, cg = u & 3;
            uint32_t so = (uint32_t)(r * 80 + cg * 16);
            size_t ga = (size_t)(m0 + r) * K + k0 + cg * 8;
            size_t gw = (size_t)(n0 + r) * K + k0 + cg * 8;
            cp_async16(st + so,         Ahi + ga);
            cp_async16(st + 10240 + so, Alo + ga);
            cp_async16(st + 20480 + so, Whi + gw);
            cp_async16(st + 30720 + so, Wlo + gw);
        }
        CP_COMMIT();
    };

    cp_chunk(0);
    for (int c = 0; c < nk; c++) {
        if (c + 1 < nk) { cp_chunk(c + 1); CP_WAIT1(); }
        else            { CP_WAIT0(); }
        __syncthreads();
        const uint32_t st = sbase + (c & 1) * GSTAGE;
        #pragma unroll
        for (int ks = 0; ks < 2; ks++) {
            uint32_t bh[8], bl[8];
            #pragma unroll
            for (int np = 0; np < 2; np++) {
                uint32_t baddr = st + 20480 +
                    (uint32_t)((warp_n * 32 + np * 16 + b_row) * 80 + ks * 32 + b_colB);
                ldsm_x4(bh[np*4+0], bh[np*4+1], bh[np*4+2], bh[np*4+3], baddr);
                ldsm_x4(bl[np*4+0], bl[np*4+1], bl[np*4+2], bl[np*4+3], baddr + 10240);
            }
            #pragma unroll
            for (int mf = 0; mf < 4; mf++) {
                uint32_t ah[4], al[4];
                uint32_t aaddr = st +
                    (uint32_t)((warp_m * 64 + mf * 16 + a_row) * 80 + ks * 32 + a_colB);
                ldsm_x4(ah[0], ah[1], ah[2], ah[3], aaddr);
                ldsm_x4(al[0], al[1], al[2], al[3], aaddr + 10240);
                #pragma unroll
                for (int nf = 0; nf < 4; nf++) {
                    const int np = nf >> 1, q = nf & 1;
                    uint32_t b0h = bh[np*4 + q*2], b1h = bh[np*4 + q*2 + 1];
                    uint32_t b0l = bl[np*4 + q*2], b1l = bl[np*4 + q*2 + 1];
                    mma16816(acc[mf][nf], ah, b0h, b1h);
                    mma16816(acc[mf][nf], ah, b0l, b1l);
                    mma16816(acc[mf][nf], al, b0h, b1h);
                }
            }
        }
        __syncthreads();
    }

    const int gID = lane >> 2, tc2 = (lane & 3) * 2;
    #pragma unroll
    for (int mf = 0; mf < 4; mf++) {
        #pragma unroll
        for (int nf = 0; nf < 4; nf++) {
            int n = n0 + warp_n * 32 + nf * 8 + tc2;
            float b0 = bias[n], b1 = bias[n + 1];
            #pragma unroll
            for (int half = 0; half < 2; half++) {
                int m = m0 + warp_m * 64 + mf * 16 + gID + half * 8;
                float v0 = acc[mf][nf][half*2 + 0] + b0;
                float v1 = acc[mf][nf][half*2 + 1] + b1;
                if (which < 5) {
                    int bb = m / Sx, srow = m - bb * Sx;
                    int h = n >> 6, d = n & 63;
                    size_t o = (((size_t)(bb * H_ + h)) * Sx + srow) * 64 + d;
                    bf16 h0 = __float2bfloat16_rn(v0), h1 = __float2bfloat16_rn(v1);
                    *reinterpret_cast<bf162*>(dh + o) = __halves2bfloat162(h0, h1);
                    bf16 l0 = __float2bfloat16_rn(v0 - __bfloat162float(h0));
                    bf16 l1 = __float2bfloat16_rn(v1 - __bfloat162float(h1));
                    *reinterpret_cast<bf162*>(dl + o) = __halves2bfloat162(l0, l1);
                } else {
                    const float2 r2 = *reinterpret_cast<const float2*>(
                        res + (size_t)m * DM_ + n);
                    float2 o = {v0 + r2.x, v1 + r2.y};
                    *reinterpret_cast<float2*>(g_Y + (size_t)m * DM_ + n) = o;
                }
            }
        }
    }
}

// ===================== tensor-core flash attention =====================
// grid (S/64, H, B), 128 threads (4 warps). Warp w owns q-rows 16w..16w+15.
// smem: Kh | Kl | Vh | Vl (64x144B each) | E (128x144B) | QE | KE (64x264B bf16)
#define AT_KH 0
#define AT_KL 9216
#define AT_VH 18432
#define AT_VL 27648
#define AT_E  36864
#define AT_QE 55296
#define AT_KE 72192
#define ATTN_SMEM_BYTES 89088

__global__ void __launch_bounds__(128)
k_attn(const float* __restrict__ mask) {
    extern __shared__ char dsm[];
    const uint32_t sb = smem_to_u32(dsm);
    const int tid = threadIdx.x;
    const int lane = tid & 31, w = tid >> 5;
    const int g = lane >> 2, t = lane & 3;
    const int sub = lane >> 3, lr = lane & 7;
    const int l0 = blockIdx.x * 64;
    const int h  = blockIdx.y;
    const int b  = blockIdx.z;
    const size_t bh = (size_t)(b * H_ + h);

    // ---- stage Q into K buffers, load A-fragments, then free the buffers ----
    {
        size_t qb = (bh * S_ + l0) * 64;
        for (int u = tid; u < 512; u += 128) {
            int r = u >> 3, c = u & 7;
            uint32_t so = (uint32_t)(r * 144 + c * 16);
            cp_async16(sb + AT_KH + so, g_Qh + qb + (size_t)r * 64 + c * 8);
            cp_async16(sb + AT_KL + so, g_Ql + qb + (size_t)r * 64 + c * 8);
        }
        CP_COMMIT(); CP_WAIT0();
    }
    __syncthreads();
    uint32_t qfh[4][4], qfl[4][4];
    #pragma unroll
    for (int ks = 0; ks < 4; ks++) {
        uint32_t ad = sb + AT_KH +
            (uint32_t)((16*w + (sub & 1)*8 + lr) * 144 + (sub >> 1)*16 + ks*32);
        ldsm_x4(qfh[ks][0], qfh[ks][1], qfh[ks][2], qfh[ks][3], ad);
        ldsm_x4(qfl[ks][0], qfl[ks][1], qfl[ks][2], qfl[ks][3], ad + 9216);
    }

    float acc[8][4] = {};
    float save[8][4];
    float mrow[2] = {-1e30f, -1e30f}, lrow[2] = {0.f, 0.f};

    // =========================== self attention ===========================
    for (int tt = 0; tt < 16; tt++) {
        const int r0 = tt * 64;
        __syncthreads();
        {   // stage K/V hi/lo + E window
            size_t kb = (bh * S_ + r0) * 64;
            for (int u = tid; u < 512; u += 128) {
                int r = u >> 3, c = u & 7;
                uint32_t so = (uint32_t)(r * 144 + c * 16);
                size_t go = kb + (size_t)r * 64 + c * 8;
                cp_async16(sb + AT_KH + so, g_Kh + go);
                cp_async16(sb + AT_KL + so, g_Kl + go);
                cp_async16(sb + AT_VH + so, g_Vh + go);
                cp_async16(sb + AT_VL + so, g_Vl + go);
            }
            const int jbase = l0 - r0 + 960;
            const bf16* Ep = g_Eh + (size_t)jbase * 64;
            for (int u = tid; u < 1016; u += 128) {
                int r = u >> 3, c = u & 7;
                cp_async16(sb + AT_E + (uint32_t)(r * 144 + c * 16),
                           Ep + (size_t)r * 64 + c * 8);
            }
            CP_COMMIT(); CP_WAIT0();
        }
        __syncthreads();

        // ---- QE / KE bias GEMMs (bf16 single precision) ----
        #pragma unroll
        for (int half = 0; half < 2; half++) {
            float qe[8][4] = {}, ke[8][4] = {};
            #pragma unroll
            for (int ks = 0; ks < 4; ks++) {
                uint32_t ka[4];
                {
                    uint32_t ad = sb + AT_KH +
                        (uint32_t)((16*w + (sub & 1)*8 + lr) * 144 + (sub >> 1)*16 + ks*32);
                    ldsm_x4(ka[0], ka[1], ka[2], ka[3], ad);
                }
                #pragma unroll
                for (int np = 0; np < 4; np++) {
                    uint32_t e0, e1, e2, e3;
                    uint32_t ad = sb + AT_E +
                        (uint32_t)((half*64 + np*16 + (sub >> 1)*8 + lr) * 144
                                   + (sub & 1)*16 + ks*32);
                    ldsm_x4(e0, e1, e2, e3, ad);
                    mma16816(qe[2*np],   qfh[ks], e0, e1);
                    mma16816(qe[2*np+1], qfh[ks], e2, e3);
                    mma16816(ke[2*np],   ka, e0, e1);
                    mma16816(ke[2*np+1], ka, e2, e3);
                }
            }
            #pragma unroll
            for (int nf = 0; nf < 8; nf++) {
                int col = half*64 + nf*8 + t*2;
                *reinterpret_cast<uint32_t*>(dsm + AT_QE + (16*w + g)*264 + col*2)
                    = pack2bf(qe[nf][0], qe[nf][1]);
                *reinterpret_cast<uint32_t*>(dsm + AT_QE + (16*w + g + 8)*264 + col*2)
                    = pack2bf(qe[nf][2], qe[nf][3]);
                *reinterpret_cast<uint32_t*>(dsm + AT_KE + (16*w + g)*264 + col*2)
                    = pack2bf(ke[nf][0], ke[nf][1]);
                *reinterpret_cast<uint32_t*>(dsm + AT_KE + (16*w + g + 8)*264 + col*2)
                    = pack2bf(ke[nf][2], ke[nf][3]);
            }
        }
        __syncthreads();

        // ---- QK^T (3-term split) ----
        float sc[8][4] = {};
        #pragma unroll
        for (int ks = 0; ks < 4; ks++) {
            #pragma unroll
            for (int np = 0; np < 4; np++) {
                uint32_t h0, h1, h2, h3, u0, u1, u2, u3;
                uint32_t ad = sb + AT_KH +
                    (uint32_t)((np*16 + (sub >> 1)*8 + lr) * 144 + (sub & 1)*16 + ks*32);
                ldsm_x4(h0, h1, h2, h3, ad);
                ldsm_x4(u0, u1, u2, u3, ad + 9216);
                mma16816(sc[2*np],   qfh[ks], h0, h1);
                mma16816(sc[2*np],   qfh[ks], u0, u1);
                mma16816(sc[2*np],   qfl[ks], h0, h1);
                mma16816(sc[2*np+1], qfh[ks], h2, h3);
                mma16816(sc[2*np+1], qfh[ks], u2, u3);
                mma16816(sc[2*np+1], qfl[ks], h2, h3);
            }
        }

        // ---- bias gather + scale + mask ----
        const bf16* QEp = reinterpret_cast<const bf16*>(dsm + AT_QE);
        const bf16* KEp = reinterpret_cast<const bf16*>(dsm + AT_KE);
        const int rl0 = 16*w + g, rl1 = rl0 + 8;
        float rowmax[2] = {-1e30f, -1e30f};
        #pragma unroll
        for (int nf = 0; nf < 8; nf++) {
            int colr = nf*8 + t*2;
            float2 mk = *reinterpret_cast<const float2*>(mask + b * S_ + r0 + colr);
            int j00 = rl0 - colr + 63;
            sc[nf][0] = (sc[nf][0] + __bfloat162float(QEp[rl0*132 + j00])
                                   + __bfloat162float(KEp[colr*132 + j00])) * 0.125f + mk.x;
            sc[nf][1] = (sc[nf][1] + __bfloat162float(QEp[rl0*132 + j00 - 1])
                                   + __bfloat162float(KEp[(colr+1)*132 + j00 - 1])) * 0.125f + mk.y;
            sc[nf][2] = (sc[nf][2] + __bfloat162float(QEp[rl1*132 + j00 + 8])
                                   + __bfloat162float(KEp[colr*132 + j00 + 8])) * 0.125f + mk.x;
            sc[nf][3] = (sc[nf][3] + __bfloat162float(QEp[rl1*132 + j00 + 7])
                                   + __bfloat162float(KEp[(colr+1)*132 + j00 + 7])) * 0.125f + mk.y;
            rowmax[0] = fmaxf(rowmax[0], fmaxf(sc[nf][0], sc[nf][1]));
            rowmax[1] = fmaxf(rowmax[1], fmaxf(sc[nf][2], sc[nf][3]));
        }
        #pragma unroll
        for (int o = 1; o <= 2; o <<= 1) {
            rowmax[0] = fmaxf(rowmax[0], __shfl_xor_sync(0xffffffffu, rowmax[0], o));
            rowmax[1] = fmaxf(rowmax[1], __shfl_xor_sync(0xffffffffu, rowmax[1], o));
        }
        float mn0 = fmaxf(mrow[0], rowmax[0]), mn1 = fmaxf(mrow[1], rowmax[1]);
        float c0 = __expf(mrow[0] - mn0), c1 = __expf(mrow[1] - mn1);
        lrow[0] *= c0; lrow[1] *= c1;
        mrow[0] = mn0; mrow[1] = mn1;
        #pragma unroll
        for (int nf = 0; nf < 8; nf++) {
            acc[nf][0] *= c0; acc[nf][1] *= c0;
            acc[nf][2] *= c1; acc[nf][3] *= c1;
        }
        uint32_t ph01[8], ph23[8], pl01[8], pl23[8];
        float rs0 = 0.f, rs1 = 0.f;
        #pragma unroll
        for (int nf = 0; nf < 8; nf++) {
            float p0 = __expf(sc[nf][0] - mn0), p1 = __expf(sc[nf][1] - mn0);
            float p2 = __expf(sc[nf][2] - mn1), p3 = __expf(sc[nf][3] - mn1);
            rs0 += p0 + p1; rs1 += p2 + p3;
            bf16 h0 = __float2bfloat16_rn(p0), h1 = __float2bfloat16_rn(p1);
            bf16 h2 = __float2bfloat16_rn(p2), h3 = __float2bfloat16_rn(p3);
            ph01[nf] = *reinterpret_cast<uint32_t*>(&(bf162&)*(bf162[]){__halves2bfloat162(h0,h1)});
            ph01[nf] = (uint32_t)*reinterpret_cast<const unsigned short*>(&h0)
                     | ((uint32_t)*reinterpret_cast<const unsigned short*>(&h1) << 16);
            ph23[nf] = (uint32_t)*reinterpret_cast<const unsigned short*>(&h2)
                     | ((uint32_t)*reinterpret_cast<const unsigned short*>(&h3) << 16);
            pl01[nf] = pack2bf(p0 - __bfloat162float(h0), p1 - __bfloat162float(h1));
            pl23[nf] = pack2bf(p2 - __bfloat162float(h2), p3 - __bfloat162float(h3));
        }
        #pragma unroll
        for (int o = 1; o <= 2; o <<= 1) {
            rs0 += __shfl_xor_sync(0xffffffffu, rs0, o);
            rs1 += __shfl_xor_sync(0xffffffffu, rs1, o);
        }
        lrow[0] += rs0; lrow[1] += rs1;

        // ---- PV (split P x split V, 3-term) ----
        #pragma unroll
        for (int ks = 0; ks < 4; ks++) {
            uint32_t aH[4] = {ph01[2*ks], ph23[2*ks], ph01[2*ks+1], ph23[2*ks+1]};
            uint32_t aL[4] = {pl01[2*ks], pl23[2*ks], pl01[2*ks+1], pl23[2*ks+1]};
            #pragma unroll
            for (int np = 0; np < 4; np++) {
                uint32_t v0, v1, v2, v3, y0, y1, y2, y3;
                uint32_t ad = sb + AT_VH +
                    (uint32_t)((16*ks + (sub & 1)*8 + lr) * 144 + ((sub >> 1)*8 + np*16)*2);
                ldsm_x4_t(v0, v1, v2, v3, ad);
                ldsm_x4_t(y0, y1, y2, y3, ad + 9216);
                mma16816(acc[2*np],   aH, v0, v1);
                mma16816(acc[2*np],   aH, y0, y1);
                mma16816(acc[2*np],   aL, v0, v1);
                mma16816(acc[2*np+1], aH, v2, v3);
                mma16816(acc[2*np+1], aH, y2, y3);
                mma16816(acc[2*np+1], aL, v2, v3);
            }
        }
    }
    {
        float i0 = 1.f / lrow[0], i1 = 1.f / lrow[1];
        #pragma unroll
        for (int nf = 0; nf < 8; nf++) {
            save[nf][0] = acc[nf][0] * i0; save[nf][1] = acc[nf][1] * i0;
            save[nf][2] = acc[nf][2] * i1; save[nf][3] = acc[nf][3] * i1;
            acc[nf][0] = acc[nf][1] = acc[nf][2] = acc[nf][3] = 0.f;
        }
        mrow[0] = mrow[1] = -1e30f; lrow[0] = lrow[1] = 0.f;
    }

    // =========================== encoder branch ===========================
    for (int tt = 0; tt < 8; tt++) {
        const int r0 = tt * 64;
        __syncthreads();
        {
            size_t kb = (bh * SE_ + r0) * 64;
            for (int u = tid; u < 512; u += 128) {
                int r = u >> 3, c = u & 7;
                uint32_t so = (uint32_t)(r * 144 + c * 16);
                size_t go = kb + (size_t)r * 64 + c * 8;
                cp_async16(sb + AT_KH + so, g_FKh + go);
                cp_async16(sb + AT_KL + so, g_FKl + go);
                cp_async16(sb + AT_VH + so, g_FVh + go);
                cp_async16(sb + AT_VL + so, g_FVl + go);
            }
            CP_COMMIT(); CP_WAIT0();
        }
        __syncthreads();

        float sc[8][4] = {};
        #pragma unroll
        for (int ks = 0; ks < 4; ks++) {
            #pragma unroll
            for (int np = 0; np < 4; np++) {
                uint32_t h0, h1, h2, h3, u0, u1, u2, u3;
                uint32_t ad = sb + AT_KH +
                    (uint32_t)((np*16 + (sub >> 1)*8 + lr) * 144 + (sub & 1)*16 + ks*32);
                ldsm_x4(h0, h1, h2, h3, ad);
                ldsm_x4(u0, u1, u2, u3, ad + 9216);
                mma16816(sc[2*np],   qfh[ks], h0, h1);
                mma16816(sc[2*np],   qfh[ks], u0, u1);
                mma16816(sc[2*np],   qfl[ks], h0, h1);
                mma16816(sc[2*np+1], qfh[ks], h2, h3);
                mma16816(sc[2*np+1], qfh[ks], u2, u3);
                mma16816(sc[2*np+1], qfl[ks], h2, h3);
            }
        }
        float rowmax[2] = {-1e30f, -1e30f};
        #pragma unroll
        for (int nf = 0; nf < 8; nf++) {
            sc[nf][0] *= 0.125f; sc[nf][1] *= 0.125f;
            sc[nf][2] *= 0.125f; sc[nf][3] *= 0.125f;
            rowmax[0] = fmaxf(rowmax[0], fmaxf(sc[nf][0], sc[nf][1]));
            rowmax[1] = fmaxf(rowmax[1], fmaxf(sc[nf][2], sc[nf][3]));
        }
        #pragma unroll
        for (int o = 1; o <= 2; o <<= 1) {
            rowmax[0] = fmaxf(rowmax[0], __shfl_xor_sync(0xffffffffu, rowmax[0], o));
            rowmax[1] = fmaxf(rowmax[1], __shfl_xor_sync(0xffffffffu, rowmax[1], o));
        }
        float mn0 = fmaxf(mrow[0], rowmax[0]), mn1 = fmaxf(mrow[1], rowmax[1]);
        float c0 = __expf(mrow[0] - mn0), c1 = __expf(mrow[1] - mn1);
        lrow[0] *= c0; lrow[1] *= c1;
        mrow[0] = mn0; mrow[1] = mn1;
        #pragma unroll
        for (int nf = 0; nf < 8; nf++) {
            acc[nf][0] *= c0; acc[nf][1] *= c0;
            acc[nf][2] *= c1; acc[nf][3] *= c1;
        }
        uint32_t ph01[8], ph23[8], pl01[8], pl23[8];
        float rs0 = 0.f, rs1 = 0.f;
        #pragma unroll
        for (int nf = 0; nf < 8; nf++) {
            float p0 = __expf(sc[nf][0] - mn0), p1 = __expf(sc[nf][1] - mn0);
            float p2 = __expf(sc[nf][2] - mn1), p3 = __expf(sc[nf][3] - mn1);
            rs0 += p0 + p1; rs1 += p2 + p3;
            bf16 h0 = __float2bfloat16_rn(p0), h1 = __float2bfloat16_rn(p1);
            bf16 h2 = __float2bfloat16_rn(p2), h3 = __float2bfloat16_rn(p3);
            ph01[nf] = (uint32_t)*reinterpret_cast<const unsigned short*>(&h0)
                     | ((uint32_t)*reinterpret_cast<const unsigned short*>(&h1) << 16);
            ph23[nf] = (uint32_t)*reinterpret_cast<const unsigned short*>(&h2)
                     | ((uint32_t)*reinterpret_cast<const unsigned short*>(&h3) << 16);
            pl01[nf] = pack2bf(p0 - __bfloat162float(h0), p1 - __bfloat162float(h1));
            pl23[nf] = pack2bf(p2 - __bfloat162float(h2), p3 - __bfloat162float(h3));
        }
        #pragma unroll
        for (int o = 1; o <= 2; o <<= 1) {
            rs0 += __shfl_xor_sync(0xffffffffu, rs0, o);
            rs1 += __shfl_xor_sync(0xffffffffu, rs1, o);
        }
        lrow[0] += rs0; lrow[1] += rs1;

        #pragma unroll
        for (int ks = 0; ks < 4; ks++) {
            uint32_t aH[4] = {ph01[2*ks], ph23[2*ks], ph01[2*ks+1], ph23[2*ks+1]};
            uint32_t aL[4] = {pl01[2*ks], pl23[2*ks], pl01[2*ks+1], pl23[2*ks+1]};
            #pragma unroll
            for (int np = 0; np < 4; np++) {
                uint32_t v0, v1, v2, v3, y0, y1, y2, y3;
                uint32_t ad = sb + AT_VH +
                    (uint32_t)((16*ks + (sub & 1)*8 + lr) * 144 + ((sub >> 1)*8 + np*16)*2);
                ldsm_x4_t(v0, v1, v2, v3, ad);
                ldsm_x4_t(y0, y1, y2, y3, ad + 9216);
                mma16816(acc[2*np],   aH, v0, v1);
                mma16816(acc[2*np],   aH, y0, y1);
                mma16816(acc[2*np],   aL, v0, v1);
                mma16816(acc[2*np+1], aH, v2, v3);
                mma16816(acc[2*np+1], aH, y2, y3);
                mma16816(acc[2*np+1], aL, v2, v3);
            }
        }
    }

    // ---- write ctx (split bf16, merged-head layout) ----
    {
        float i0 = 1.f / lrow[0], i1 = 1.f / lrow[1];
        const int rl0 = l0 + 16*w + g, rl1 = rl0 + 8;
        #pragma unroll
        for (int nf = 0; nf < 8; nf++) {
            int col = nf*8 + t*2;
            float f00 = save[nf][0] + acc[nf][0]*i0;
            float f01 = save[nf][1] + acc[nf][1]*i0;
            float f10 = save[nf][2] + acc[nf][2]*i1;
            float f11 = save[nf][3] + acc[nf][3]*i1;
            size_t b0a = (((size_t)b * S_ + rl0) * H_ + h) * 64 + col;
            size_t b1a = (((size_t)b * S_ + rl1) * H_ + h) * 64 + col;
            bf16 h00 = __float2bfloat16_rn(f00), h01 = __float2bfloat16_rn(f01);
            bf16 h10 = __float2bfloat16_rn(f10), h11 = __float2bfloat16_rn(f11);
            *reinterpret_cast<bf162*>(g_ctx_hi + b0a) = __halves2bfloat162(h00, h01);
            *reinterpret_cast<bf162*>(g_ctx_hi + b1a) = __halves2bfloat162(h10, h11);
            *reinterpret_cast<bf162*>(g_ctx_lo + b0a) = __halves2bfloat162(
                __float2bfloat16_rn(f00 - __bfloat162float(h00)),
                __float2bfloat16_rn(f01 - __bfloat162float(h01)));
            *reinterpret_cast<bf162*>(g_ctx_lo + b1a) = __halves2bfloat162(
                __float2bfloat16_rn(f10 - __bfloat162float(h10)),
                __float2bfloat16_rn(f11 - __bfloat162float(h11)));
        }
    }
}

// ---------------- LayerNorm ----------------------
__global__ void k_ln(const float* __restrict__ ga, const float* __restrict__ be,
                     float* __restrict__ out) {
    const int row = blockIdx.x;
    const int tid = threadIdx.x;
    const float* y = g_Y + (size_t)row * DM_;
    float4 tv = *reinterpret_cast<const float4*>(y + tid * 4);
    float s  = tv.x + tv.y + tv.z + tv.w;
    float s2 = tv.x * tv.x + tv.y * tv.y + tv.z * tv.z + tv.w * tv.w;
    #pragma unroll
    for (int o = 16; o > 0; o >>= 1) {
        s  += __shfl_xor_sync(0xffffffffu, s,  o);
        s2 += __shfl_xor_sync(0xffffffffu, s2, o);
    }
    __shared__ float sh[16];
    int w = tid >> 5, lane = tid & 31;
    if (lane == 0) { sh[w] = s; sh[8 + w] = s2; }
    __syncthreads();
    if (tid == 0) {
        float S = 0.f, S2 = 0.f;
        #pragma unroll
        for (int i = 0; i < 8; i++) { S += sh[i]; S2 += sh[8 + i]; }
        sh[0] = S; sh[1] = S2;
    }
    __syncthreads();
    float mu  = sh[0] * (1.f / DM_);
    float var = sh[1] * (1.f / DM_) - mu * mu;
    float r   = rsqrtf(var + 1e-12f);
    int c = tid * 4;
    float4 gv = *reinterpret_cast<const float4*>(ga + c);
    float4 bv = *reinterpret_cast<const float4*>(be + c);
    float4 o;
    o.x = (tv.x - mu) * r * gv.x + bv.x;
    o.y = (tv.y - mu) * r * gv.y + bv.y;
    o.z = (tv.z - mu) * r * gv.z + bv.z;
    o.w = (tv.w - mu) * r * gv.w + bv.w;
    *reinterpret_cast<float4*>(out + (size_t)row * DM_ + c) = o;
}

// ---------------- launch ----------------------------------------------------
extern "C" void kernel_launch(void* const* d_in, const int* in_sizes, int n_in,
                              void* d_out, int out_size) {
    (void)in_sizes; (void)n_in; (void)out_size;
    const float* hs   = (const float*)d_in[0];
    const float* mask = (const float*)d_in[1];
    const float* enc  = (const float*)d_in[2];
    const float* Wq   = (const float*)d_in[3];
    const float* bq   = (const float*)d_in[4];
    const float* Wk   = (const float*)d_in[5];
    const float* bk   = (const float*)d_in[6];
    const float* Wv   = (const float*)d_in[7];
    const float* bv   = (const float*)d_in[8];
    const float* Wfk  = (const float*)d_in[9];
    const float* bfk  = (const float*)d_in[10];
    const float* Wfv  = (const float*)d_in[11];
    const float* bfv  = (const float*)d_in[12];
    const float* E    = (const float*)d_in[13];
    const float* Wo   = (const float*)d_in[14];
    const float* bo   = (const float*)d_in[15];
    const float* lg   = (const float*)d_in[16];
    const float* lb   = (const float*)d_in[17];
    float* out = (float*)d_out;

    static bool attr_set = false;
    if (!attr_set) {
        cudaFuncSetAttribute(k_attn, cudaFuncAttributeMaxDynamicSharedMemorySize, ATTN_SMEM_BYTES);
        cudaFuncSetAttribute(k_gemm, cudaFuncAttributeMaxDynamicSharedMemorySize, GEMM_SMEM_BYTES);
        attr_set = true;
    }

    k_cvt<<<4096, 256>>>(hs,  0, B_*S_*DM_/4);
    k_cvt<<<1024, 256>>>(enc, 1, B_*SE_*DF_/4);
    k_cvt<<<1024, 256>>>(Wq,  2, 1048576/4);
    k_cvt<<<1024, 256>>>(Wk,  3, 1048576/4);
    k_cvt<<<1024, 256>>>(Wv,  4, 1048576/4);
    k_cvt<<<1024, 256>>>(Wo,  5, 1048576/4);
    k_cvt<<< 512, 256>>>(Wfk, 6, 524288/4);
    k_cvt<<< 512, 256>>>(Wfv, 7, 524288/4);
    k_cvt<<< 128, 256>>>(E,   8, 2047*64/4);

    k_gemm<<<dim3(8, 32), 256, GEMM_SMEM_BYTES>>>(bq,  nullptr, 0);
    k_gemm<<<dim3(8, 32), 256, GEMM_SMEM_BYTES>>>(bk,  nullptr, 1);
    k_gemm<<<dim3(8, 32), 256, GEMM_SMEM_BYTES>>>(bv,  nullptr, 2);
    k_gemm<<<dim3(8, 16), 256, GEMM_SMEM_BYTES>>>(bfk, nullptr, 3);
    k_gemm<<<dim3(8, 16), 256, GEMM_SMEM_BYTES>>>(bfv, nullptr, 4);

    k_attn<<<dim3(16, 16, 4), 128, ATTN_SMEM_BYTES>>>(mask);

    k_gemm<<<dim3(8, 32), 256, GEMM_SMEM_BYTES>>>(bo, hs, 5);
    k_ln<<<4096, 256>>>(lg, lb, out);
}

// round 5
// speedup vs baseline: 5.4861x; 1.2347x over previous
#include <cuda_runtime.h>
#include <cuda_bf16.h>
#include <cstdint>

#define B_  4
#define S_  1024
#define DM_ 1024
#define H_  16
#define D_  64
#define SE_ 512
#define DF_ 512

typedef __nv_bfloat16 bf16;
typedef __nv_bfloat162 bf162;

// ===================== scratch =====================
__device__ float g_Y[B_*S_*DM_];

__device__ __align__(16) bf16 g_Qh [B_*H_*S_ *D_];
__device__ __align__(16) bf16 g_Ql [B_*H_*S_ *D_];
__device__ __align__(16) bf16 g_Kh [B_*H_*S_ *D_];
__device__ __align__(16) bf16 g_Kl [B_*H_*S_ *D_];
__device__ __align__(16) bf16 g_Vh [B_*H_*S_ *D_];
__device__ __align__(16) bf16 g_Vl [B_*H_*S_ *D_];
__device__ __align__(16) bf16 g_FKh[B_*H_*SE_*D_];
__device__ __align__(16) bf16 g_FKl[B_*H_*SE_*D_];
__device__ __align__(16) bf16 g_FVh[B_*H_*SE_*D_];
__device__ __align__(16) bf16 g_FVl[B_*H_*SE_*D_];
__device__ __align__(16) bf16 g_Eh [2047*64];
__device__ __align__(16) bf16 g_El [2047*64];

__device__ __align__(16) bf16 g_hs_hi [B_*S_*DM_];
__device__ __align__(16) bf16 g_hs_lo [B_*S_*DM_];
__device__ __align__(16) bf16 g_enc_hi[B_*SE_*DF_];
__device__ __align__(16) bf16 g_enc_lo[B_*SE_*DF_];
__device__ __align__(16) bf16 g_ctx_hi[B_*S_*DM_];
__device__ __align__(16) bf16 g_ctx_lo[B_*S_*DM_];
#define WOFF_Q  0
#define WOFF_K  1048576
#define WOFF_V  2097152
#define WOFF_O  3145728
#define WOFF_FK 4194304
#define WOFF_FV 4718592
__device__ __align__(16) bf16 g_wb_hi[5242880];
__device__ __align__(16) bf16 g_wb_lo[5242880];

// ===================== helpers =====================
__device__ __forceinline__ uint32_t smem_to_u32(const void* p) {
    uint32_t a;
    asm("{ .reg .u64 t; cvta.to.shared.u64 t, %1; cvt.u32.u64 %0, t; }" : "=r"(a) : "l"(p));
    return a;
}
__device__ __forceinline__ void cp_async16(uint32_t saddr, const void* gptr) {
    asm volatile("cp.async.cg.shared.global [%0], [%1], 16;" :: "r"(saddr), "l"(gptr));
}
#define CP_COMMIT() asm volatile("cp.async.commit_group;" ::: "memory")
#define CP_WAIT0()  asm volatile("cp.async.wait_group 0;" ::: "memory")
#define CP_WAIT1()  asm volatile("cp.async.wait_group 1;" ::: "memory")
#define CP_WAIT2()  asm volatile("cp.async.wait_group 2;" ::: "memory")
__device__ __forceinline__ void ldsm_x4(uint32_t& r0, uint32_t& r1, uint32_t& r2,
                                        uint32_t& r3, uint32_t addr) {
    asm volatile("ldmatrix.sync.aligned.m8n8.x4.shared.b16 {%0,%1,%2,%3}, [%4];"
                 : "=r"(r0), "=r"(r1), "=r"(r2), "=r"(r3) : "r"(addr));
}
__device__ __forceinline__ void ldsm_x4_t(uint32_t& r0, uint32_t& r1, uint32_t& r2,
                                          uint32_t& r3, uint32_t addr) {
    asm volatile("ldmatrix.sync.aligned.m8n8.x4.trans.shared.b16 {%0,%1,%2,%3}, [%4];"
                 : "=r"(r0), "=r"(r1), "=r"(r2), "=r"(r3) : "r"(addr));
}
__device__ __forceinline__ void mma16816(float* c, const uint32_t* a,
                                         uint32_t b0, uint32_t b1) {
    asm volatile(
        "mma.sync.aligned.m16n8k16.row.col.f32.bf16.bf16.f32 "
        "{%0,%1,%2,%3}, {%4,%5,%6,%7}, {%8,%9}, {%0,%1,%2,%3};"
        : "+f"(c[0]), "+f"(c[1]), "+f"(c[2]), "+f"(c[3])
        : "r"(a[0]), "r"(a[1]), "r"(a[2]), "r"(a[3]), "r"(b0), "r"(b1));
}
__device__ __forceinline__ uint32_t pack2bf(float lo, float hi) {
    bf162 v = __floats2bfloat162_rn(lo, hi);
    return *reinterpret_cast<uint32_t*>(&v);
}

// ===================== merged fp32 -> (hi,lo) bf16 split =====================
__device__ __forceinline__ void cvt_one(const float* __restrict__ src,
                                        bf16* hi, bf16* lo, int i) {
    float4 v = reinterpret_cast<const float4*>(src)[i];
    bf16 hx = __float2bfloat16_rn(v.x);
    bf16 hy = __float2bfloat16_rn(v.y);
    bf16 hz = __float2bfloat16_rn(v.z);
    bf16 hw = __float2bfloat16_rn(v.w);
    bf16 lx = __float2bfloat16_rn(v.x - __bfloat162float(hx));
    bf16 ly = __float2bfloat16_rn(v.y - __bfloat162float(hy));
    bf16 lz = __float2bfloat16_rn(v.z - __bfloat162float(hz));
    bf16 lw = __float2bfloat16_rn(v.w - __bfloat162float(hw));
    bf162* h2 = reinterpret_cast<bf162*>(hi);
    bf162* l2 = reinterpret_cast<bf162*>(lo);
    h2[2*i]   = __halves2bfloat162(hx, hy);
    h2[2*i+1] = __halves2bfloat162(hz, hw);
    l2[2*i]   = __halves2bfloat162(lx, ly);
    l2[2*i+1] = __halves2bfloat162(lz, lw);
}

__global__ void __launch_bounds__(256)
k_cvt_all(const float* hs, const float* enc, const float* Wq, const float* Wk,
          const float* Wv, const float* Wo, const float* Wfk, const float* Wfv,
          const float* E) {
    int blk = blockIdx.x, tid = threadIdx.x;
    const float* src; bf16 *hi, *lo; int lb, n4;
    if      (blk < 4096)  { src=hs;  hi=g_hs_hi;           lo=g_hs_lo;           lb=0;     n4=1048576; }
    else if (blk < 5120)  { src=enc; hi=g_enc_hi;          lo=g_enc_lo;          lb=4096;  n4=262144; }
    else if (blk < 6144)  { src=Wq;  hi=g_wb_hi+WOFF_Q;    lo=g_wb_lo+WOFF_Q;    lb=5120;  n4=262144; }
    else if (blk < 7168)  { src=Wk;  hi=g_wb_hi+WOFF_K;    lo=g_wb_lo+WOFF_K;    lb=6144;  n4=262144; }
    else if (blk < 8192)  { src=Wv;  hi=g_wb_hi+WOFF_V;    lo=g_wb_lo+WOFF_V;    lb=7168;  n4=262144; }
    else if (blk < 9216)  { src=Wo;  hi=g_wb_hi+WOFF_O;    lo=g_wb_lo+WOFF_O;    lb=8192;  n4=262144; }
    else if (blk < 9728)  { src=Wfk; hi=g_wb_hi+WOFF_FK;   lo=g_wb_lo+WOFF_FK;   lb=9216;  n4=131072; }
    else if (blk < 10240) { src=Wfv; hi=g_wb_hi+WOFF_FV;   lo=g_wb_lo+WOFF_FV;   lb=9728;  n4=131072; }
    else                  { src=E;   hi=g_Eh;              lo=g_El;              lb=10240; n4=32752; }
    int i = (blk - lb) * 256 + tid;
    if (i < n4) cvt_one(src, hi, lo, i);
}

// ===================== mma.sync split-bf16 GEMM =====================
#define GSTAGE 40960
#define GEMM_SMEM_BYTES (2*GSTAGE)

__global__ void __launch_bounds__(256) k_gemm(const float* __restrict__ b0p,
                                              const float* __restrict__ b1p,
                                              const float* __restrict__ b2p,
                                              const float* __restrict__ res,
                                              int base) {
    extern __shared__ char dsm[];
    const uint32_t sbase = smem_to_u32(dsm);
    const int tid = threadIdx.x;
    const int lane = tid & 31, wid = tid >> 5;
    const int warp_m = wid & 1, warp_n = wid >> 1;
    const int m0 = blockIdx.y * 128, n0 = blockIdx.x * 128;
    const int which = base + blockIdx.z;
    const float* bias = blockIdx.z == 0 ? b0p : blockIdx.z == 1 ? b1p : b2p;

    const bf16 *Ahi, *Alo, *Whi, *Wlo;
    bf16 *dh = nullptr, *dl = nullptr;
    int K, Sx;
    switch (which) {
        case 0: Ahi=g_hs_hi;  Alo=g_hs_lo;  Whi=g_wb_hi+WOFF_Q;  Wlo=g_wb_lo+WOFF_Q;  dh=g_Qh;  dl=g_Ql;  K=1024; Sx=1024; break;
        case 1: Ahi=g_hs_hi;  Alo=g_hs_lo;  Whi=g_wb_hi+WOFF_K;  Wlo=g_wb_lo+WOFF_K;  dh=g_Kh;  dl=g_Kl;  K=1024; Sx=1024; break;
        case 2: Ahi=g_hs_hi;  Alo=g_hs_lo;  Whi=g_wb_hi+WOFF_V;  Wlo=g_wb_lo+WOFF_V;  dh=g_Vh;  dl=g_Vl;  K=1024; Sx=1024; break;
        case 3: Ahi=g_enc_hi; Alo=g_enc_lo; Whi=g_wb_hi+WOFF_FK; Wlo=g_wb_lo+WOFF_FK; dh=g_FKh; dl=g_FKl; K=512;  Sx=512;  break;
        case 4: Ahi=g_enc_hi; Alo=g_enc_lo; Whi=g_wb_hi+WOFF_FV; Wlo=g_wb_lo+WOFF_FV; dh=g_FVh; dl=g_FVl; K=512;  Sx=512;  break;
        default:Ahi=g_ctx_hi; Alo=g_ctx_lo; Whi=g_wb_hi+WOFF_O;  Wlo=g_wb_lo+WOFF_O;  K=1024; Sx=1024; break;
    }
    const int nk = K >> 5;

    const int sub = lane >> 3, lr = lane & 7;
    const int a_row = (sub & 1) * 8 + lr, a_colB = (sub >> 1) * 16;
    const int b_row = (sub >> 1) * 8 + lr, b_colB = (sub & 1) * 16;

    float acc[4][4][4] = {};

    auto cp_chunk = [&](int c) {
        const int s = c & 1;
        const uint32_t st = sbase + s * GSTAGE;
        const int k0 = c * 32;
        #pragma unroll
        for (int i = 0; i < 2; i++) {
            int u = tid + i * 256;
            int r = u >> 2, cg = u & 3;
            uint32_t so = (uint32_t)(r * 80 + cg * 16);
            size_t ga = (size_t)(m0 + r) * K + k0 + cg * 8;
            size_t gw = (size_t)(n0 + r) * K + k0 + cg * 8;
            cp_async16(st + so,         Ahi + ga);
            cp_async16(st + 10240 + so, Alo + ga);
            cp_async16(st + 20480 + so, Whi + gw);
            cp_async16(st + 30720 + so, Wlo + gw);
        }
        CP_COMMIT();
    };

    cp_chunk(0);
    for (int c = 0; c < nk; c++) {
        if (c + 1 < nk) { cp_chunk(c + 1); CP_WAIT1(); }
        else            { CP_WAIT0(); }
        __syncthreads();
        const uint32_t st = sbase + (c & 1) * GSTAGE;
        #pragma unroll
        for (int ks = 0; ks < 2; ks++) {
            uint32_t bh[8], bl[8];
            #pragma unroll
            for (int np = 0; np < 2; np++) {
                uint32_t baddr = st + 20480 +
                    (uint32_t)((warp_n * 32 + np * 16 + b_row) * 80 + ks * 32 + b_colB);
                ldsm_x4(bh[np*4+0], bh[np*4+1], bh[np*4+2], bh[np*4+3], baddr);
                ldsm_x4(bl[np*4+0], bl[np*4+1], bl[np*4+2], bl[np*4+3], baddr + 10240);
            }
            #pragma unroll
            for (int mf = 0; mf < 4; mf++) {
                uint32_t ah[4], al[4];
                uint32_t aaddr = st +
                    (uint32_t)((warp_m * 64 + mf * 16 + a_row) * 80 + ks * 32 + a_colB);
                ldsm_x4(ah[0], ah[1], ah[2], ah[3], aaddr);
                ldsm_x4(al[0], al[1], al[2], al[3], aaddr + 10240);
                #pragma unroll
                for (int nf = 0; nf < 4; nf++) {
                    const int np = nf >> 1, q = nf & 1;
                    uint32_t b0 = bh[np*4 + q*2], b1 = bh[np*4 + q*2 + 1];
                    uint32_t c0 = bl[np*4 + q*2], c1 = bl[np*4 + q*2 + 1];
                    mma16816(acc[mf][nf], ah, b0, b1);
                    mma16816(acc[mf][nf], ah, c0, c1);
                    mma16816(acc[mf][nf], al, b0, b1);
                }
            }
        }
        __syncthreads();
    }

    const int gID = lane >> 2, tc2 = (lane & 3) * 2;
    #pragma unroll
    for (int mf = 0; mf < 4; mf++) {
        #pragma unroll
        for (int nf = 0; nf < 4; nf++) {
            int n = n0 + warp_n * 32 + nf * 8 + tc2;
            float bb0 = bias[n], bb1 = bias[n + 1];
            #pragma unroll
            for (int half = 0; half < 2; half++) {
                int m = m0 + warp_m * 64 + mf * 16 + gID + half * 8;
                float v0 = acc[mf][nf][half*2 + 0] + bb0;
                float v1 = acc[mf][nf][half*2 + 1] + bb1;
                if (which < 5) {
                    int bb = m / Sx, srow = m - bb * Sx;
                    int h = n >> 6, d = n & 63;
                    size_t o = (((size_t)(bb * H_ + h)) * Sx + srow) * 64 + d;
                    bf16 h0 = __float2bfloat16_rn(v0), h1 = __float2bfloat16_rn(v1);
                    *reinterpret_cast<bf162*>(dh + o) = __halves2bfloat162(h0, h1);
                    bf16 l0 = __float2bfloat16_rn(v0 - __bfloat162float(h0));
                    bf16 l1 = __float2bfloat16_rn(v1 - __bfloat162float(h1));
                    *reinterpret_cast<bf162*>(dl + o) = __halves2bfloat162(l0, l1);
                } else {
                    const float2 r2 = *reinterpret_cast<const float2*>(
                        res + (size_t)m * DM_ + n);
                    float2 o = {v0 + r2.x, v1 + r2.y};
                    *reinterpret_cast<float2*>(g_Y + (size_t)m * DM_ + n) = o;
                }
            }
        }
    }
}

// ===================== tensor-core flash attention =====================
// grid (S/64, H, B), 128 threads (4 warps). Warp w owns q-rows 16w..16w+15.
// Per-warp bias windows: QE cols [16w,16w+80), KE cols [16(3-w),16(3-w)+80).
#define AT_KH 0
#define AT_KL 9216
#define AT_VH 18432
#define AT_VL 27648
#define AT_E  36864
#define AT_QE 55296
#define AT_KE 66560
#define ATTN_SMEM_BYTES 77824

__global__ void __launch_bounds__(128)
k_attn(const float* __restrict__ mask) {
    extern __shared__ char dsm[];
    const uint32_t sb = smem_to_u32(dsm);
    const int tid = threadIdx.x;
    const int lane = tid & 31, w = tid >> 5;
    const int g = lane >> 2, t = lane & 3;
    const int sub = lane >> 3, lr = lane & 7;
    const int l0 = blockIdx.x * 64;
    const int h  = blockIdx.y;
    const int b  = blockIdx.z;
    const size_t bh = (size_t)(b * H_ + h);

    // ---- stage Q into K buffers, load A-fragments ----
    {
        size_t qb = (bh * S_ + l0) * 64;
        for (int u = tid; u < 512; u += 128) {
            int r = u >> 3, c = u & 7;
            uint32_t so = (uint32_t)(r * 144 + c * 16);
            cp_async16(sb + AT_KH + so, g_Qh + qb + (size_t)r * 64 + c * 8);
            cp_async16(sb + AT_KL + so, g_Ql + qb + (size_t)r * 64 + c * 8);
        }
        CP_COMMIT(); CP_WAIT0();
    }
    __syncthreads();
    uint32_t qfh[4][4], qfl[4][4];
    #pragma unroll
    for (int ks = 0; ks < 4; ks++) {
        uint32_t ad = sb + AT_KH +
            (uint32_t)((16*w + (sub & 1)*8 + lr) * 144 + (sub >> 1)*16 + ks*32);
        ldsm_x4(qfh[ks][0], qfh[ks][1], qfh[ks][2], qfh[ks][3], ad);
        ldsm_x4(qfl[ks][0], qfl[ks][1], qfl[ks][2], qfl[ks][3], ad + 9216);
    }

    float acc[8][4] = {};
    float save[8][4];
    float mrow[2] = {-1e30f, -1e30f}, lrow[2] = {0.f, 0.f};

    // =========================== self attention ===========================
    for (int tt = 0; tt < 16; tt++) {
        const int r0 = tt * 64;
        __syncthreads();
        // group 1: E window
        {
            const int jbase = l0 - r0 + 960;
            const bf16* Ep = g_Eh + (size_t)jbase * 64;
            for (int u = tid; u < 1016; u += 128) {
                int r = u >> 3, c = u & 7;
                cp_async16(sb + AT_E + (uint32_t)(r * 144 + c * 16),
                           Ep + (size_t)r * 64 + c * 8);
            }
            CP_COMMIT();
        }
        // group 2: K hi/lo
        {
            size_t kb = (bh * S_ + r0) * 64;
            for (int u = tid; u < 512; u += 128) {
                int r = u >> 3, c = u & 7;
                uint32_t so = (uint32_t)(r * 144 + c * 16);
                size_t go = kb + (size_t)r * 64 + c * 8;
                cp_async16(sb + AT_KH + so, g_Kh + go);
                cp_async16(sb + AT_KL + so, g_Kl + go);
            }
            CP_COMMIT();
        }
        // group 3: V hi/lo
        {
            size_t kb = (bh * S_ + r0) * 64;
            for (int u = tid; u < 512; u += 128) {
                int r = u >> 3, c = u & 7;
                uint32_t so = (uint32_t)(r * 144 + c * 16);
                size_t go = kb + (size_t)r * 64 + c * 8;
                cp_async16(sb + AT_VH + so, g_Vh + go);
                cp_async16(sb + AT_VL + so, g_Vl + go);
            }
            CP_COMMIT();
        }

        CP_WAIT2(); __syncthreads();   // E ready

        // ---- QE pass (per-warp 80-col window starting at 16w) ----
        {
            float qe[10][4] = {};
            #pragma unroll
            for (int ks = 0; ks < 4; ks++) {
                #pragma unroll
                for (int np = 0; np < 5; np++) {
                    uint32_t e0, e1, e2, e3;
                    uint32_t ad = sb + AT_E +
                        (uint32_t)((16*w + np*16 + (sub >> 1)*8 + lr) * 144
                                   + (sub & 1)*16 + ks*32);
                    ldsm_x4(e0, e1, e2, e3, ad);
                    mma16816(qe[2*np],   qfh[ks], e0, e1);
                    mma16816(qe[2*np+1], qfh[ks], e2, e3);
                }
            }
            #pragma unroll
            for (int nf = 0; nf < 10; nf++) {
                uint32_t c2 = (uint32_t)((nf*8 + t*2) * 2);
                *reinterpret_cast<uint32_t*>(dsm + AT_QE + (16*w + g)*176 + c2)
                    = pack2bf(qe[nf][0], qe[nf][1]);
                *reinterpret_cast<uint32_t*>(dsm + AT_QE + (16*w + g + 8)*176 + c2)
                    = pack2bf(qe[nf][2], qe[nf][3]);
            }
        }

        CP_WAIT1(); __syncthreads();   // K ready

        // ---- KE pass (per-warp 80-col window starting at 16(3-w)) ----
        {
            float ke[10][4] = {};
            const int kb16 = 16 * (3 - w);
            #pragma unroll
            for (int ks = 0; ks < 4; ks++) {
                uint32_t ka[4];
                uint32_t aad = sb + AT_KH +
                    (uint32_t)((16*w + (sub & 1)*8 + lr) * 144 + (sub >> 1)*16 + ks*32);
                ldsm_x4(ka[0], ka[1], ka[2], ka[3], aad);
                #pragma unroll
                for (int np = 0; np < 5; np++) {
                    uint32_t e0, e1, e2, e3;
                    uint32_t ad = sb + AT_E +
                        (uint32_t)((kb16 + np*16 + (sub >> 1)*8 + lr) * 144
                                   + (sub & 1)*16 + ks*32);
                    ldsm_x4(e0, e1, e2, e3, ad);
                    mma16816(ke[2*np],   ka, e0, e1);
                    mma16816(ke[2*np+1], ka, e2, e3);
                }
            }
            #pragma unroll
            for (int nf = 0; nf < 10; nf++) {
                uint32_t c2 = (uint32_t)((nf*8 + t*2) * 2);
                *reinterpret_cast<uint32_t*>(dsm + AT_KE + (16*w + g)*176 + c2)
                    = pack2bf(ke[nf][0], ke[nf][1]);
                *reinterpret_cast<uint32_t*>(dsm + AT_KE + (16*w + g + 8)*176 + c2)
                    = pack2bf(ke[nf][2], ke[nf][3]);
            }
        }

        // ---- QK^T (3-term split) ----
        float sc[8][4] = {};
        #pragma unroll
        for (int ks = 0; ks < 4; ks++) {
            #pragma unroll
            for (int np = 0; np < 4; np++) {
                uint32_t h0, h1, h2, h3, u0, u1, u2, u3;
                uint32_t ad = sb + AT_KH +
                    (uint32_t)((np*16 + (sub >> 1)*8 + lr) * 144 + (sub & 1)*16 + ks*32);
                ldsm_x4(h0, h1, h2, h3, ad);
                ldsm_x4(u0, u1, u2, u3, ad + 9216);
                mma16816(sc[2*np],   qfh[ks], h0, h1);
                mma16816(sc[2*np],   qfh[ks], u0, u1);
                mma16816(sc[2*np],   qfl[ks], h0, h1);
                mma16816(sc[2*np+1], qfh[ks], h2, h3);
                mma16816(sc[2*np+1], qfh[ks], u2, u3);
                mma16816(sc[2*np+1], qfl[ks], h2, h3);
            }
        }
        __syncthreads();   // QE/KE stores visible to all warps

        // ---- bias gather + scale + mask ----
        const bf16* QEp = reinterpret_cast<const bf16*>(dsm + AT_QE);
        const bf16* KEp = reinterpret_cast<const bf16*>(dsm + AT_KE);
        float rowmax[2] = {-1e30f, -1e30f};
        #pragma unroll
        for (int nf = 0; nf < 8; nf++) {
            int colr = nf*8 + t*2;
            float2 mk = *reinterpret_cast<const float2*>(mask + b * S_ + r0 + colr);
            int rq0 = (16*w + g) * 88, rq1 = rq0 + 8*88;
            int cq = g - colr + 63;
            int rk = 16*w + g + 15 - (colr & 15);
            sc[nf][0] = (sc[nf][0] + __bfloat162float(QEp[rq0 + cq])
                                   + __bfloat162float(KEp[colr*88 + rk])) * 0.125f + mk.x;
            sc[nf][1] = (sc[nf][1] + __bfloat162float(QEp[rq0 + cq - 1])
                                   + __bfloat162float(KEp[(colr+1)*88 + rk - 1])) * 0.125f + mk.y;
            sc[nf][2] = (sc[nf][2] + __bfloat162float(QEp[rq1 + cq + 8])
                                   + __bfloat162float(KEp[colr*88 + rk + 8])) * 0.125f + mk.x;
            sc[nf][3] = (sc[nf][3] + __bfloat162float(QEp[rq1 + cq + 7])
                                   + __bfloat162float(KEp[(colr+1)*88 + rk + 7])) * 0.125f + mk.y;
            rowmax[0] = fmaxf(rowmax[0], fmaxf(sc[nf][0], sc[nf][1]));
            rowmax[1] = fmaxf(rowmax[1], fmaxf(sc[nf][2], sc[nf][3]));
        }
        #pragma unroll
        for (int o = 1; o <= 2; o <<= 1) {
            rowmax[0] = fmaxf(rowmax[0], __shfl_xor_sync(0xffffffffu, rowmax[0], o));
            rowmax[1] = fmaxf(rowmax[1], __shfl_xor_sync(0xffffffffu, rowmax[1], o));
        }
        float mn0 = fmaxf(mrow[0], rowmax[0]), mn1 = fmaxf(mrow[1], rowmax[1]);
        float c0 = __expf(mrow[0] - mn0), c1 = __expf(mrow[1] - mn1);
        lrow[0] *= c0; lrow[1] *= c1;
        mrow[0] = mn0; mrow[1] = mn1;
        #pragma unroll
        for (int nf = 0; nf < 8; nf++) {
            acc[nf][0] *= c0; acc[nf][1] *= c0;
            acc[nf][2] *= c1; acc[nf][3] *= c1;
        }
        uint32_t ph01[8], ph23[8], pl01[8], pl23[8];
        float rs0 = 0.f, rs1 = 0.f;
        #pragma unroll
        for (int nf = 0; nf < 8; nf++) {
            float p0 = __expf(sc[nf][0] - mn0), p1 = __expf(sc[nf][1] - mn0);
            float p2 = __expf(sc[nf][2] - mn1), p3 = __expf(sc[nf][3] - mn1);
            rs0 += p0 + p1; rs1 += p2 + p3;
            bf16 h0 = __float2bfloat16_rn(p0), h1 = __float2bfloat16_rn(p1);
            bf16 h2 = __float2bfloat16_rn(p2), h3 = __float2bfloat16_rn(p3);
            ph01[nf] = (uint32_t)*reinterpret_cast<const unsigned short*>(&h0)
                     | ((uint32_t)*reinterpret_cast<const unsigned short*>(&h1) << 16);
            ph23[nf] = (uint32_t)*reinterpret_cast<const unsigned short*>(&h2)
                     | ((uint32_t)*reinterpret_cast<const unsigned short*>(&h3) << 16);
            pl01[nf] = pack2bf(p0 - __bfloat162float(h0), p1 - __bfloat162float(h1));
            pl23[nf] = pack2bf(p2 - __bfloat162float(h2), p3 - __bfloat162float(h3));
        }
        #pragma unroll
        for (int o = 1; o <= 2; o <<= 1) {
            rs0 += __shfl_xor_sync(0xffffffffu, rs0, o);
            rs1 += __shfl_xor_sync(0xffffffffu, rs1, o);
        }
        lrow[0] += rs0; lrow[1] += rs1;

        CP_WAIT0(); __syncthreads();   // V ready

        // ---- PV (split P x split V, 3-term) ----
        #pragma unroll
        for (int ks = 0; ks < 4; ks++) {
            uint32_t aH[4] = {ph01[2*ks], ph23[2*ks], ph01[2*ks+1], ph23[2*ks+1]};
            uint32_t aL[4] = {pl01[2*ks], pl23[2*ks], pl01[2*ks+1], pl23[2*ks+1]};
            #pragma unroll
            for (int np = 0; np < 4; np++) {
                uint32_t v0, v1, v2, v3, y0, y1, y2, y3;
                uint32_t ad = sb + AT_VH +
                    (uint32_t)((16*ks + (sub & 1)*8 + lr) * 144 + ((sub >> 1)*8 + np*16)*2);
                ldsm_x4_t(v0, v1, v2, v3, ad);
                ldsm_x4_t(y0, y1, y2, y3, ad + 9216);
                mma16816(acc[2*np],   aH, v0, v1);
                mma16816(acc[2*np],   aH, y0, y1);
                mma16816(acc[2*np],   aL, v0, v1);
                mma16816(acc[2*np+1], aH, v2, v3);
                mma16816(acc[2*np+1], aH, y2, y3);
                mma16816(acc[2*np+1], aL, v2, v3);
            }
        }
    }
    {
        float i0 = 1.f / lrow[0], i1 = 1.f / lrow[1];
        #pragma unroll
        for (int nf = 0; nf < 8; nf++) {
            save[nf][0] = acc[nf][0] * i0; save[nf][1] = acc[nf][1] * i0;
            save[nf][2] = acc[nf][2] * i1; save[nf][3] = acc[nf][3] * i1;
            acc[nf][0] = acc[nf][1] = acc[nf][2] = acc[nf][3] = 0.f;
        }
        mrow[0] = mrow[1] = -1e30f; lrow[0] = lrow[1] = 0.f;
    }

    // =========================== encoder branch ===========================
    for (int tt = 0; tt < 8; tt++) {
        const int r0 = tt * 64;
        __syncthreads();
        {
            size_t kb = (bh * SE_ + r0) * 64;
            for (int u = tid; u < 512; u += 128) {
                int r = u >> 3, c = u & 7;
                uint32_t so = (uint32_t)(r * 144 + c * 16);
                size_t go = kb + (size_t)r * 64 + c * 8;
                cp_async16(sb + AT_KH + so, g_FKh + go);
                cp_async16(sb + AT_KL + so, g_FKl + go);
            }
            CP_COMMIT();
            for (int u = tid; u < 512; u += 128) {
                int r = u >> 3, c = u & 7;
                uint32_t so = (uint32_t)(r * 144 + c * 16);
                size_t go = kb + (size_t)r * 64 + c * 8;
                cp_async16(sb + AT_VH + so, g_FVh + go);
                cp_async16(sb + AT_VL + so, g_FVl + go);
            }
            CP_COMMIT();
        }
        CP_WAIT1(); __syncthreads();   // K ready

        float sc[8][4] = {};
        #pragma unroll
        for (int ks = 0; ks < 4; ks++) {
            #pragma unroll
            for (int np = 0; np < 4; np++) {
                uint32_t h0, h1, h2, h3, u0, u1, u2, u3;
                uint32_t ad = sb + AT_KH +
                    (uint32_t)((np*16 + (sub >> 1)*8 + lr) * 144 + (sub & 1)*16 + ks*32);
                ldsm_x4(h0, h1, h2, h3, ad);
                ldsm_x4(u0, u1, u2, u3, ad + 9216);
                mma16816(sc[2*np],   qfh[ks], h0, h1);
                mma16816(sc[2*np],   qfh[ks], u0, u1);
                mma16816(sc[2*np],   qfl[ks], h0, h1);
                mma16816(sc[2*np+1], qfh[ks], h2, h3);
                mma16816(sc[2*np+1], qfh[ks], u2, u3);
                mma16816(sc[2*np+1], qfl[ks], h2, h3);
            }
        }
        float rowmax[2] = {-1e30f, -1e30f};
        #pragma unroll
        for (int nf = 0; nf < 8; nf++) {
            sc[nf][0] *= 0.125f; sc[nf][1] *= 0.125f;
            sc[nf][2] *= 0.125f; sc[nf][3] *= 0.125f;
            rowmax[0] = fmaxf(rowmax[0], fmaxf(sc[nf][0], sc[nf][1]));
            rowmax[1] = fmaxf(rowmax[1], fmaxf(sc[nf][2], sc[nf][3]));
        }
        #pragma unroll
        for (int o = 1; o <= 2; o <<= 1) {
            rowmax[0] = fmaxf(rowmax[0], __shfl_xor_sync(0xffffffffu, rowmax[0], o));
            rowmax[1] = fmaxf(rowmax[1], __shfl_xor_sync(0xffffffffu, rowmax[1], o));
        }
        float mn0 = fmaxf(mrow[0], rowmax[0]), mn1 = fmaxf(mrow[1], rowmax[1]);
        float c0 = __expf(mrow[0] - mn0), c1 = __expf(mrow[1] - mn1);
        lrow[0] *= c0; lrow[1] *= c1;
        mrow[0] = mn0; mrow[1] = mn1;
        #pragma unroll
        for (int nf = 0; nf < 8; nf++) {
            acc[nf][0] *= c0; acc[nf][1] *= c0;
            acc[nf][2] *= c1; acc[nf][3] *= c1;
        }
        uint32_t ph01[8], ph23[8], pl01[8], pl23[8];
        float rs0 = 0.f, rs1 = 0.f;
        #pragma unroll
        for (int nf = 0; nf < 8; nf++) {
            float p0 = __expf(sc[nf][0] - mn0), p1 = __expf(sc[nf][1] - mn0);
            float p2 = __expf(sc[nf][2] - mn1), p3 = __expf(sc[nf][3] - mn1);
            rs0 += p0 + p1; rs1 += p2 + p3;
            bf16 h0 = __float2bfloat16_rn(p0), h1 = __float2bfloat16_rn(p1);
            bf16 h2 = __float2bfloat16_rn(p2), h3 = __float2bfloat16_rn(p3);
            ph01[nf] = (uint32_t)*reinterpret_cast<const unsigned short*>(&h0)
                     | ((uint32_t)*reinterpret_cast<const unsigned short*>(&h1) << 16);
            ph23[nf] = (uint32_t)*reinterpret_cast<const unsigned short*>(&h2)
                     | ((uint32_t)*reinterpret_cast<const unsigned short*>(&h3) << 16);
            pl01[nf] = pack2bf(p0 - __bfloat162float(h0), p1 - __bfloat162float(h1));
            pl23[nf] = pack2bf(p2 - __bfloat162float(h2), p3 - __bfloat162float(h3));
        }
        #pragma unroll
        for (int o = 1; o <= 2; o <<= 1) {
            rs0 += __shfl_xor_sync(0xffffffffu, rs0, o);
            rs1 += __shfl_xor_sync(0xffffffffu, rs1, o);
        }
        lrow[0] += rs0; lrow[1] += rs1;

        CP_WAIT0(); __syncthreads();   // V ready

        #pragma unroll
        for (int ks = 0; ks < 4; ks++) {
            uint32_t aH[4] = {ph01[2*ks], ph23[2*ks], ph01[2*ks+1], ph23[2*ks+1]};
            uint32_t aL[4] = {pl01[2*ks], pl23[2*ks], pl01[2*ks+1], pl23[2*ks+1]};
            #pragma unroll
            for (int np = 0; np < 4; np++) {
                uint32_t v0, v1, v2, v3, y0, y1, y2, y3;
                uint32_t ad = sb + AT_VH +
                    (uint32_t)((16*ks + (sub & 1)*8 + lr) * 144 + ((sub >> 1)*8 + np*16)*2);
                ldsm_x4_t(v0, v1, v2, v3, ad);
                ldsm_x4_t(y0, y1, y2, y3, ad + 9216);
                mma16816(acc[2*np],   aH, v0, v1);
                mma16816(acc[2*np],   aH, y0, y1);
                mma16816(acc[2*np],   aL, v0, v1);
                mma16816(acc[2*np+1], aH, v2, v3);
                mma16816(acc[2*np+1], aH, y2, y3);
                mma16816(acc[2*np+1], aL, v2, v3);
            }
        }
    }

    // ---- write ctx (split bf16, merged-head layout) ----
    {
        float i0 = 1.f / lrow[0], i1 = 1.f / lrow[1];
        const int rl0 = l0 + 16*w + g, rl1 = rl0 + 8;
        #pragma unroll
        for (int nf = 0; nf < 8; nf++) {
            int col = nf*8 + t*2;
            float f00 = save[nf][0] + acc[nf][0]*i0;
            float f01 = save[nf][1] + acc[nf][1]*i0;
            float f10 = save[nf][2] + acc[nf][2]*i1;
            float f11 = save[nf][3] + acc[nf][3]*i1;
            size_t b0a = (((size_t)b * S_ + rl0) * H_ + h) * 64 + col;
            size_t b1a = (((size_t)b * S_ + rl1) * H_ + h) * 64 + col;
            bf16 h00 = __float2bfloat16_rn(f00), h01 = __float2bfloat16_rn(f01);
            bf16 h10 = __float2bfloat16_rn(f10), h11 = __float2bfloat16_rn(f11);
            *reinterpret_cast<bf162*>(g_ctx_hi + b0a) = __halves2bfloat162(h00, h01);
            *reinterpret_cast<bf162*>(g_ctx_hi + b1a) = __halves2bfloat162(h10, h11);
            *reinterpret_cast<bf162*>(g_ctx_lo + b0a) = __halves2bfloat162(
                __float2bfloat16_rn(f00 - __bfloat162float(h00)),
                __float2bfloat16_rn(f01 - __bfloat162float(h01)));
            *reinterpret_cast<bf162*>(g_ctx_lo + b1a) = __halves2bfloat162(
                __float2bfloat16_rn(f10 - __bfloat162float(h10)),
                __float2bfloat16_rn(f11 - __bfloat162float(h11)));
        }
    }
}

// ---------------- LayerNorm ----------------------
__global__ void k_ln(const float* __restrict__ ga, const float* __restrict__ be,
                     float* __restrict__ out) {
    const int row = blockIdx.x;
    const int tid = threadIdx.x;
    const float* y = g_Y + (size_t)row * DM_;
    float4 tv = *reinterpret_cast<const float4*>(y + tid * 4);
    float s  = tv.x + tv.y + tv.z + tv.w;
    float s2 = tv.x * tv.x + tv.y * tv.y + tv.z * tv.z + tv.w * tv.w;
    #pragma unroll
    for (int o = 16; o > 0; o >>= 1) {
        s  += __shfl_xor_sync(0xffffffffu, s,  o);
        s2 += __shfl_xor_sync(0xffffffffu, s2, o);
    }
    __shared__ float sh[16];
    int w = tid >> 5, lane = tid & 31;
    if (lane == 0) { sh[w] = s; sh[8 + w] = s2; }
    __syncthreads();
    if (tid == 0) {
        float S = 0.f, S2 = 0.f;
        #pragma unroll
        for (int i = 0; i < 8; i++) { S += sh[i]; S2 += sh[8 + i]; }
        sh[0] = S; sh[1] = S2;
    }
    __syncthreads();
    float mu  = sh[0] * (1.f / DM_);
    float var = sh[1] * (1.f / DM_) - mu * mu;
    float r   = rsqrtf(var + 1e-12f);
    int c = tid * 4;
    float4 gv = *reinterpret_cast<const float4*>(ga + c);
    float4 bv = *reinterpret_cast<const float4*>(be + c);
    float4 o;
    o.x = (tv.x - mu) * r * gv.x + bv.x;
    o.y = (tv.y - mu) * r * gv.y + bv.y;
    o.z = (tv.z - mu) * r * gv.z + bv.z;
    o.w = (tv.w - mu) * r * gv.w + bv.w;
    *reinterpret_cast<float4*>(out + (size_t)row * DM_ + c) = o;
}

// ---------------- launch ----------------------------------------------------
extern "C" void kernel_launch(void* const* d_in, const int* in_sizes, int n_in,
                              void* d_out, int out_size) {
    (void)in_sizes; (void)n_in; (void)out_size;
    const float* hs   = (const float*)d_in[0];
    const float* mask = (const float*)d_in[1];
    const float* enc  = (const float*)d_in[2];
    const float* Wq   = (const float*)d_in[3];
    const float* bq   = (const float*)d_in[4];
    const float* Wk   = (const float*)d_in[5];
    const float* bk   = (const float*)d_in[6];
    const float* Wv   = (const float*)d_in[7];
    const float* bv   = (const float*)d_in[8];
    const float* Wfk  = (const float*)d_in[9];
    const float* bfk  = (const float*)d_in[10];
    const float* Wfv  = (const float*)d_in[11];
    const float* bfv  = (const float*)d_in[12];
    const float* E    = (const float*)d_in[13];
    const float* Wo   = (const float*)d_in[14];
    const float* bo   = (const float*)d_in[15];
    const float* lg   = (const float*)d_in[16];
    const float* lb   = (const float*)d_in[17];
    float* out = (float*)d_out;

    static bool attr_set = false;
    if (!attr_set) {
        cudaFuncSetAttribute(k_attn, cudaFuncAttributeMaxDynamicSharedMemorySize, ATTN_SMEM_BYTES);
        cudaFuncSetAttribute(k_gemm, cudaFuncAttributeMaxDynamicSharedMemorySize, GEMM_SMEM_BYTES);
        attr_set = true;
    }

    k_cvt_all<<<10368, 256>>>(hs, enc, Wq, Wk, Wv, Wo, Wfk, Wfv, E);

    k_gemm<<<dim3(8, 32, 3), 256, GEMM_SMEM_BYTES>>>(bq, bk, bv, nullptr, 0);
    k_gemm<<<dim3(8, 16, 2), 256, GEMM_SMEM_BYTES>>>(bfk, bfv, nullptr, nullptr, 3);

    k_attn<<<dim3(16, 16, 4), 128, ATTN_SMEM_BYTES>>>(mask);

    k_gemm<<<dim3(8, 32, 1), 256, GEMM_SMEM_BYTES>>>(bo, nullptr, nullptr, hs, 5);
    k_ln<<<4096, 256>>>(lg, lb, out);
}

// round 6
// speedup vs baseline: 9.9944x; 1.8218x over previous
#include <cuda_runtime.h>
#include <cuda_bf16.h>
#include <cstdint>

#define B_  4
#define S_  1024
#define DM_ 1024
#define H_  16
#define D_  64
#define SE_ 512
#define DF_ 512

typedef __nv_bfloat16 bf16;
typedef __nv_bfloat162 bf162;

// ===================== scratch =====================
__device__ float g_Y[B_*S_*DM_];

__device__ __align__(16) bf16 g_Q  [B_*H_*S_ *D_];
__device__ __align__(16) bf16 g_K  [B_*H_*S_ *D_];
__device__ __align__(16) bf16 g_V  [B_*H_*S_ *D_];
__device__ __align__(16) bf16 g_FK [B_*H_*SE_*D_];
__device__ __align__(16) bf16 g_FV [B_*H_*SE_*D_];
__device__ __align__(16) bf16 g_E  [2047*64];

__device__ __align__(16) bf16 g_hs  [B_*S_*DM_];
__device__ __align__(16) bf16 g_enc [B_*SE_*DF_];
__device__ __align__(16) bf16 g_ctx [B_*S_*DM_];
#define WOFF_Q  0
#define WOFF_K  1048576
#define WOFF_V  2097152
#define WOFF_O  3145728
#define WOFF_FK 4194304
#define WOFF_FV 4718592
__device__ __align__(16) bf16 g_wb[5242880];

// ===================== helpers =====================
__device__ __forceinline__ uint32_t smem_to_u32(const void* p) {
    uint32_t a;
    asm("{ .reg .u64 t; cvta.to.shared.u64 t, %1; cvt.u32.u64 %0, t; }" : "=r"(a) : "l"(p));
    return a;
}
__device__ __forceinline__ void cp_async16(uint32_t saddr, const void* gptr) {
    asm volatile("cp.async.cg.shared.global [%0], [%1], 16;" :: "r"(saddr), "l"(gptr));
}
#define CP_COMMIT() asm volatile("cp.async.commit_group;" ::: "memory")
#define CP_WAIT0()  asm volatile("cp.async.wait_group 0;" ::: "memory")
#define CP_WAIT1()  asm volatile("cp.async.wait_group 1;" ::: "memory")
#define CP_WAIT2()  asm volatile("cp.async.wait_group 2;" ::: "memory")
__device__ __forceinline__ void ldsm_x4(uint32_t& r0, uint32_t& r1, uint32_t& r2,
                                        uint32_t& r3, uint32_t addr) {
    asm volatile("ldmatrix.sync.aligned.m8n8.x4.shared.b16 {%0,%1,%2,%3}, [%4];"
                 : "=r"(r0), "=r"(r1), "=r"(r2), "=r"(r3) : "r"(addr));
}
__device__ __forceinline__ void ldsm_x4_t(uint32_t& r0, uint32_t& r1, uint32_t& r2,
                                          uint32_t& r3, uint32_t addr) {
    asm volatile("ldmatrix.sync.aligned.m8n8.x4.trans.shared.b16 {%0,%1,%2,%3}, [%4];"
                 : "=r"(r0), "=r"(r1), "=r"(r2), "=r"(r3) : "r"(addr));
}
__device__ __forceinline__ void mma16816(float* c, const uint32_t* a,
                                         uint32_t b0, uint32_t b1) {
    asm volatile(
        "mma.sync.aligned.m16n8k16.row.col.f32.bf16.bf16.f32 "
        "{%0,%1,%2,%3}, {%4,%5,%6,%7}, {%8,%9}, {%0,%1,%2,%3};"
        : "+f"(c[0]), "+f"(c[1]), "+f"(c[2]), "+f"(c[3])
        : "r"(a[0]), "r"(a[1]), "r"(a[2]), "r"(a[3]), "r"(b0), "r"(b1));
}
__device__ __forceinline__ uint32_t pack2bf(float lo, float hi) {
    bf162 v = __floats2bfloat162_rn(lo, hi);
    return *reinterpret_cast<uint32_t*>(&v);
}

// ===================== merged fp32 -> bf16 convert =====================
__device__ __forceinline__ void cvt_one(const float* __restrict__ src, bf16* dst, int i) {
    float4 v = reinterpret_cast<const float4*>(src)[i];
    bf162* d2 = reinterpret_cast<bf162*>(dst);
    d2[2*i]   = __floats2bfloat162_rn(v.x, v.y);
    d2[2*i+1] = __floats2bfloat162_rn(v.z, v.w);
}

__global__ void __launch_bounds__(256)
k_cvt_all(const float* hs, const float* enc, const float* Wq, const float* Wk,
          const float* Wv, const float* Wo, const float* Wfk, const float* Wfv,
          const float* E) {
    int blk = blockIdx.x, tid = threadIdx.x;
    const float* src; bf16* dst; int lb, n4;
    if      (blk < 4096)  { src=hs;  dst=g_hs;           lb=0;     n4=1048576; }
    else if (blk < 5120)  { src=enc; dst=g_enc;          lb=4096;  n4=262144; }
    else if (blk < 6144)  { src=Wq;  dst=g_wb+WOFF_Q;    lb=5120;  n4=262144; }
    else if (blk < 7168)  { src=Wk;  dst=g_wb+WOFF_K;    lb=6144;  n4=262144; }
    else if (blk < 8192)  { src=Wv;  dst=g_wb+WOFF_V;    lb=7168;  n4=262144; }
    else if (blk < 9216)  { src=Wo;  dst=g_wb+WOFF_O;    lb=8192;  n4=262144; }
    else if (blk < 9728)  { src=Wfk; dst=g_wb+WOFF_FK;   lb=9216;  n4=131072; }
    else if (blk < 10240) { src=Wfv; dst=g_wb+WOFF_FV;   lb=9728;  n4=131072; }
    else                  { src=E;   dst=g_E;            lb=10240; n4=32752; }
    int i = (blk - lb) * 256 + tid;
    if (i < n4) cvt_one(src, dst, i);
}

// ===================== mma.sync bf16 GEMM =====================
#define GSTAGE 20480
#define GEMM_SMEM_BYTES (2*GSTAGE)

__global__ void __launch_bounds__(256) k_gemm(const float* __restrict__ b0p,
                                              const float* __restrict__ b1p,
                                              const float* __restrict__ b2p,
                                              const float* __restrict__ res,
                                              int base) {
    extern __shared__ char dsm[];
    const uint32_t sbase = smem_to_u32(dsm);
    const int tid = threadIdx.x;
    const int lane = tid & 31, wid = tid >> 5;
    const int warp_m = wid & 1, warp_n = wid >> 1;
    const int m0 = blockIdx.y * 128, n0 = blockIdx.x * 128;
    const int which = base + blockIdx.z;
    const float* bias = blockIdx.z == 0 ? b0p : blockIdx.z == 1 ? b1p : b2p;

    const bf16 *A, *W;
    bf16* dst = nullptr;
    int K, Sx;
    switch (which) {
        case 0: A=g_hs;  W=g_wb+WOFF_Q;  dst=g_Q;  K=1024; Sx=1024; break;
        case 1: A=g_hs;  W=g_wb+WOFF_K;  dst=g_K;  K=1024; Sx=1024; break;
        case 2: A=g_hs;  W=g_wb+WOFF_V;  dst=g_V;  K=1024; Sx=1024; break;
        case 3: A=g_enc; W=g_wb+WOFF_FK; dst=g_FK; K=512;  Sx=512;  break;
        case 4: A=g_enc; W=g_wb+WOFF_FV; dst=g_FV; K=512;  Sx=512;  break;
        default:A=g_ctx; W=g_wb+WOFF_O;  K=1024; Sx=1024; break;
    }
    const int nk = K >> 5;

    const int sub = lane >> 3, lr = lane & 7;
    const int a_row = (sub & 1) * 8 + lr, a_colB = (sub >> 1) * 16;
    const int b_row = (sub >> 1) * 8 + lr, b_colB = (sub & 1) * 16;

    float acc[4][4][4] = {};

    auto cp_chunk = [&](int c) {
        const int s = c & 1;
        const uint32_t st = sbase + s * GSTAGE;
        const int k0 = c * 32;
        #pragma unroll
        for (int i = 0; i < 2; i++) {
            int u = tid + i * 256;
            int r = u >> 2, cg = u & 3;
            uint32_t so = (uint32_t)(r * 80 + cg * 16);
            cp_async16(st + so,         A + (size_t)(m0 + r) * K + k0 + cg * 8);
            cp_async16(st + 10240 + so, W + (size_t)(n0 + r) * K + k0 + cg * 8);
        }
        CP_COMMIT();
    };

    cp_chunk(0);
    for (int c = 0; c < nk; c++) {
        if (c + 1 < nk) { cp_chunk(c + 1); CP_WAIT1(); }
        else            { CP_WAIT0(); }
        __syncthreads();
        const uint32_t st = sbase + (c & 1) * GSTAGE;
        #pragma unroll
        for (int ks = 0; ks < 2; ks++) {
            uint32_t bh[8];
            #pragma unroll
            for (int np = 0; np < 2; np++) {
                uint32_t baddr = st + 10240 +
                    (uint32_t)((warp_n * 32 + np * 16 + b_row) * 80 + ks * 32 + b_colB);
                ldsm_x4(bh[np*4+0], bh[np*4+1], bh[np*4+2], bh[np*4+3], baddr);
            }
            #pragma unroll
            for (int mf = 0; mf < 4; mf++) {
                uint32_t ah[4];
                uint32_t aaddr = st +
                    (uint32_t)((warp_m * 64 + mf * 16 + a_row) * 80 + ks * 32 + a_colB);
                ldsm_x4(ah[0], ah[1], ah[2], ah[3], aaddr);
                #pragma unroll
                for (int nf = 0; nf < 4; nf++) {
                    const int np = nf >> 1, q = nf & 1;
                    mma16816(acc[mf][nf], ah, bh[np*4 + q*2], bh[np*4 + q*2 + 1]);
                }
            }
        }
        __syncthreads();
    }

    const int gID = lane >> 2, tc2 = (lane & 3) * 2;
    #pragma unroll
    for (int mf = 0; mf < 4; mf++) {
        #pragma unroll
        for (int nf = 0; nf < 4; nf++) {
            int n = n0 + warp_n * 32 + nf * 8 + tc2;
            float bb0 = bias[n], bb1 = bias[n + 1];
            #pragma unroll
            for (int half = 0; half < 2; half++) {
                int m = m0 + warp_m * 64 + mf * 16 + gID + half * 8;
                float v0 = acc[mf][nf][half*2 + 0] + bb0;
                float v1 = acc[mf][nf][half*2 + 1] + bb1;
                if (which < 5) {
                    int bb = m / Sx, srow = m - bb * Sx;
                    int h = n >> 6, d = n & 63;
                    size_t o = (((size_t)(bb * H_ + h)) * Sx + srow) * 64 + d;
                    *reinterpret_cast<bf162*>(dst + o) = __floats2bfloat162_rn(v0, v1);
                } else {
                    const float2 r2 = *reinterpret_cast<const float2*>(
                        res + (size_t)m * DM_ + n);
                    float2 o = {v0 + r2.x, v1 + r2.y};
                    *reinterpret_cast<float2*>(g_Y + (size_t)m * DM_ + n) = o;
                }
            }
        }
    }
}

// ===================== tensor-core flash attention (bf16) =====================
// grid (S/64, H, B), 128 threads (4 warps). Warp w owns q-rows 16w..16w+15.
#define AT_K  0
#define AT_V  9216
#define AT_E  18432
#define AT_QE 36864
#define AT_KE 48128
#define ATTN_SMEM_BYTES 59392

__global__ void __launch_bounds__(128, 3)
k_attn(const float* __restrict__ mask) {
    extern __shared__ char dsm[];
    const uint32_t sb = smem_to_u32(dsm);
    const int tid = threadIdx.x;
    const int lane = tid & 31, w = tid >> 5;
    const int g = lane >> 2, t = lane & 3;
    const int sub = lane >> 3, lr = lane & 7;
    const int l0 = blockIdx.x * 64;
    const int h  = blockIdx.y;
    const int b  = blockIdx.z;
    const size_t bh = (size_t)(b * H_ + h);

    // ---- stage Q into K buffer, load A-fragments ----
    {
        size_t qb = (bh * S_ + l0) * 64;
        for (int u = tid; u < 512; u += 128) {
            int r = u >> 3, c = u & 7;
            cp_async16(sb + AT_K + (uint32_t)(r * 144 + c * 16),
                       g_Q + qb + (size_t)r * 64 + c * 8);
        }
        CP_COMMIT(); CP_WAIT0();
    }
    __syncthreads();
    uint32_t qf[4][4];
    #pragma unroll
    for (int ks = 0; ks < 4; ks++) {
        uint32_t ad = sb + AT_K +
            (uint32_t)((16*w + (sub & 1)*8 + lr) * 144 + (sub >> 1)*16 + ks*32);
        ldsm_x4(qf[ks][0], qf[ks][1], qf[ks][2], qf[ks][3], ad);
    }

    float acc[8][4] = {};
    float save[8][4];
    float mrow[2] = {-1e30f, -1e30f}, lrow[2] = {0.f, 0.f};

    // =========================== self attention ===========================
    for (int tt = 0; tt < 16; tt++) {
        const int r0 = tt * 64;
        __syncthreads();
        // group 1: E window
        {
            const int jbase = l0 - r0 + 960;
            const bf16* Ep = g_E + (size_t)jbase * 64;
            for (int u = tid; u < 1016; u += 128) {
                int r = u >> 3, c = u & 7;
                cp_async16(sb + AT_E + (uint32_t)(r * 144 + c * 16),
                           Ep + (size_t)r * 64 + c * 8);
            }
            CP_COMMIT();
        }
        // group 2: K
        {
            size_t kb = (bh * S_ + r0) * 64;
            for (int u = tid; u < 512; u += 128) {
                int r = u >> 3, c = u & 7;
                cp_async16(sb + AT_K + (uint32_t)(r * 144 + c * 16),
                           g_K + kb + (size_t)r * 64 + c * 8);
            }
            CP_COMMIT();
        }
        // group 3: V
        {
            size_t kb = (bh * S_ + r0) * 64;
            for (int u = tid; u < 512; u += 128) {
                int r = u >> 3, c = u & 7;
                cp_async16(sb + AT_V + (uint32_t)(r * 144 + c * 16),
                           g_V + kb + (size_t)r * 64 + c * 8);
            }
            CP_COMMIT();
        }

        CP_WAIT2(); __syncthreads();   // E ready

        // ---- QE pass (per-warp 80-col window starting at 16w) ----
        {
            float qe[10][4] = {};
            #pragma unroll
            for (int ks = 0; ks < 4; ks++) {
                #pragma unroll
                for (int np = 0; np < 5; np++) {
                    uint32_t e0, e1, e2, e3;
                    uint32_t ad = sb + AT_E +
                        (uint32_t)((16*w + np*16 + (sub >> 1)*8 + lr) * 144
                                   + (sub & 1)*16 + ks*32);
                    ldsm_x4(e0, e1, e2, e3, ad);
                    mma16816(qe[2*np],   qf[ks], e0, e1);
                    mma16816(qe[2*np+1], qf[ks], e2, e3);
                }
            }
            #pragma unroll
            for (int nf = 0; nf < 10; nf++) {
                uint32_t c2 = (uint32_t)((nf*8 + t*2) * 2);
                *reinterpret_cast<uint32_t*>(dsm + AT_QE + (16*w + g)*176 + c2)
                    = pack2bf(qe[nf][0], qe[nf][1]);
                *reinterpret_cast<uint32_t*>(dsm + AT_QE + (16*w + g + 8)*176 + c2)
                    = pack2bf(qe[nf][2], qe[nf][3]);
            }
        }

        CP_WAIT1(); __syncthreads();   // K ready

        // ---- KE pass (per-warp 80-col window starting at 16(3-w)) ----
        {
            float ke[10][4] = {};
            const int kb16 = 16 * (3 - w);
            #pragma unroll
            for (int ks = 0; ks < 4; ks++) {
                uint32_t ka[4];
                uint32_t aad = sb + AT_K +
                    (uint32_t)((16*w + (sub & 1)*8 + lr) * 144 + (sub >> 1)*16 + ks*32);
                ldsm_x4(ka[0], ka[1], ka[2], ka[3], aad);
                #pragma unroll
                for (int np = 0; np < 5; np++) {
                    uint32_t e0, e1, e2, e3;
                    uint32_t ad = sb + AT_E +
                        (uint32_t)((kb16 + np*16 + (sub >> 1)*8 + lr) * 144
                                   + (sub & 1)*16 + ks*32);
                    ldsm_x4(e0, e1, e2, e3, ad);
                    mma16816(ke[2*np],   ka, e0, e1);
                    mma16816(ke[2*np+1], ka, e2, e3);
                }
            }
            #pragma unroll
            for (int nf = 0; nf < 10; nf++) {
                uint32_t c2 = (uint32_t)((nf*8 + t*2) * 2);
                *reinterpret_cast<uint32_t*>(dsm + AT_KE + (16*w + g)*176 + c2)
                    = pack2bf(ke[nf][0], ke[nf][1]);
                *reinterpret_cast<uint32_t*>(dsm + AT_KE + (16*w + g + 8)*176 + c2)
                    = pack2bf(ke[nf][2], ke[nf][3]);
            }
        }

        // ---- QK^T ----
        float sc[8][4] = {};
        #pragma unroll
        for (int ks = 0; ks < 4; ks++) {
            #pragma unroll
            for (int np = 0; np < 4; np++) {
                uint32_t h0, h1, h2, h3;
                uint32_t ad = sb + AT_K +
                    (uint32_t)((np*16 + (sub >> 1)*8 + lr) * 144 + (sub & 1)*16 + ks*32);
                ldsm_x4(h0, h1, h2, h3, ad);
                mma16816(sc[2*np],   qf[ks], h0, h1);
                mma16816(sc[2*np+1], qf[ks], h2, h3);
            }
        }
        __syncthreads();   // QE/KE stores visible to all warps

        // ---- bias gather + scale + mask ----
        const bf16* QEp = reinterpret_cast<const bf16*>(dsm + AT_QE);
        const bf16* KEp = reinterpret_cast<const bf16*>(dsm + AT_KE);
        float rowmax[2] = {-1e30f, -1e30f};
        #pragma unroll
        for (int nf = 0; nf < 8; nf++) {
            int colr = nf*8 + t*2;
            float2 mk = *reinterpret_cast<const float2*>(mask + b * S_ + r0 + colr);
            int rq0 = (16*w + g) * 88, rq1 = rq0 + 8*88;
            int cq = g - colr + 63;
            int rk = 16*w + g + 15 - (colr & 15);
            sc[nf][0] = (sc[nf][0] + __bfloat162float(QEp[rq0 + cq])
                                   + __bfloat162float(KEp[colr*88 + rk])) * 0.125f + mk.x;
            sc[nf][1] = (sc[nf][1] + __bfloat162float(QEp[rq0 + cq - 1])
                                   + __bfloat162float(KEp[(colr+1)*88 + rk - 1])) * 0.125f + mk.y;
            sc[nf][2] = (sc[nf][2] + __bfloat162float(QEp[rq1 + cq + 8])
                                   + __bfloat162float(KEp[colr*88 + rk + 8])) * 0.125f + mk.x;
            sc[nf][3] = (sc[nf][3] + __bfloat162float(QEp[rq1 + cq + 7])
                                   + __bfloat162float(KEp[(colr+1)*88 + rk + 7])) * 0.125f + mk.y;
            rowmax[0] = fmaxf(rowmax[0], fmaxf(sc[nf][0], sc[nf][1]));
            rowmax[1] = fmaxf(rowmax[1], fmaxf(sc[nf][2], sc[nf][3]));
        }
        #pragma unroll
        for (int o = 1; o <= 2; o <<= 1) {
            rowmax[0] = fmaxf(rowmax[0], __shfl_xor_sync(0xffffffffu, rowmax[0], o));
            rowmax[1] = fmaxf(rowmax[1], __shfl_xor_sync(0xffffffffu, rowmax[1], o));
        }
        float mn0 = fmaxf(mrow[0], rowmax[0]), mn1 = fmaxf(mrow[1], rowmax[1]);
        float c0 = __expf(mrow[0] - mn0), c1 = __expf(mrow[1] - mn1);
        lrow[0] *= c0; lrow[1] *= c1;
        mrow[0] = mn0; mrow[1] = mn1;
        #pragma unroll
        for (int nf = 0; nf < 8; nf++) {
            acc[nf][0] *= c0; acc[nf][1] *= c0;
            acc[nf][2] *= c1; acc[nf][3] *= c1;
        }
        uint32_t ph01[8], ph23[8];
        float rs0 = 0.f, rs1 = 0.f;
        #pragma unroll
        for (int nf = 0; nf < 8; nf++) {
            float p0 = __expf(sc[nf][0] - mn0), p1 = __expf(sc[nf][1] - mn0);
            float p2 = __expf(sc[nf][2] - mn1), p3 = __expf(sc[nf][3] - mn1);
            rs0 += p0 + p1; rs1 += p2 + p3;
            ph01[nf] = pack2bf(p0, p1);
            ph23[nf] = pack2bf(p2, p3);
        }
        #pragma unroll
        for (int o = 1; o <= 2; o <<= 1) {
            rs0 += __shfl_xor_sync(0xffffffffu, rs0, o);
            rs1 += __shfl_xor_sync(0xffffffffu, rs1, o);
        }
        lrow[0] += rs0; lrow[1] += rs1;

        CP_WAIT0(); __syncthreads();   // V ready

        // ---- PV ----
        #pragma unroll
        for (int ks = 0; ks < 4; ks++) {
            uint32_t aH[4] = {ph01[2*ks], ph23[2*ks], ph01[2*ks+1], ph23[2*ks+1]};
            #pragma unroll
            for (int np = 0; np < 4; np++) {
                uint32_t v0, v1, v2, v3;
                uint32_t ad = sb + AT_V +
                    (uint32_t)((16*ks + (sub & 1)*8 + lr) * 144 + ((sub >> 1)*8 + np*16)*2);
                ldsm_x4_t(v0, v1, v2, v3, ad);
                mma16816(acc[2*np],   aH, v0, v1);
                mma16816(acc[2*np+1], aH, v2, v3);
            }
        }
    }
    {
        float i0 = 1.f / lrow[0], i1 = 1.f / lrow[1];
        #pragma unroll
        for (int nf = 0; nf < 8; nf++) {
            save[nf][0] = acc[nf][0] * i0; save[nf][1] = acc[nf][1] * i0;
            save[nf][2] = acc[nf][2] * i1; save[nf][3] = acc[nf][3] * i1;
            acc[nf][0] = acc[nf][1] = acc[nf][2] = acc[nf][3] = 0.f;
        }
        mrow[0] = mrow[1] = -1e30f; lrow[0] = lrow[1] = 0.f;
    }

    // =========================== encoder branch ===========================
    for (int tt = 0; tt < 8; tt++) {
        const int r0 = tt * 64;
        __syncthreads();
        {
            size_t kb = (bh * SE_ + r0) * 64;
            for (int u = tid; u < 512; u += 128) {
                int r = u >> 3, c = u & 7;
                cp_async16(sb + AT_K + (uint32_t)(r * 144 + c * 16),
                           g_FK + kb + (size_t)r * 64 + c * 8);
            }
            CP_COMMIT();
            for (int u = tid; u < 512; u += 128) {
                int r = u >> 3, c = u & 7;
                cp_async16(sb + AT_V + (uint32_t)(r * 144 + c * 16),
                           g_FV + kb + (size_t)r * 64 + c * 8);
            }
            CP_COMMIT();
        }
        CP_WAIT1(); __syncthreads();   // K ready

        float sc[8][4] = {};
        #pragma unroll
        for (int ks = 0; ks < 4; ks++) {
            #pragma unroll
            for (int np = 0; np < 4; np++) {
                uint32_t h0, h1, h2, h3;
                uint32_t ad = sb + AT_K +
                    (uint32_t)((np*16 + (sub >> 1)*8 + lr) * 144 + (sub & 1)*16 + ks*32);
                ldsm_x4(h0, h1, h2, h3, ad);
                mma16816(sc[2*np],   qf[ks], h0, h1);
                mma16816(sc[2*np+1], qf[ks], h2, h3);
            }
        }
        float rowmax[2] = {-1e30f, -1e30f};
        #pragma unroll
        for (int nf = 0; nf < 8; nf++) {
            sc[nf][0] *= 0.125f; sc[nf][1] *= 0.125f;
            sc[nf][2] *= 0.125f; sc[nf][3] *= 0.125f;
            rowmax[0] = fmaxf(rowmax[0], fmaxf(sc[nf][0], sc[nf][1]));
            rowmax[1] = fmaxf(rowmax[1], fmaxf(sc[nf][2], sc[nf][3]));
        }
        #pragma unroll
        for (int o = 1; o <= 2; o <<= 1) {
            rowmax[0] = fmaxf(rowmax[0], __shfl_xor_sync(0xffffffffu, rowmax[0], o));
            rowmax[1] = fmaxf(rowmax[1], __shfl_xor_sync(0xffffffffu, rowmax[1], o));
        }
        float mn0 = fmaxf(mrow[0], rowmax[0]), mn1 = fmaxf(mrow[1], rowmax[1]);
        float c0 = __expf(mrow[0] - mn0), c1 = __expf(mrow[1] - mn1);
        lrow[0] *= c0; lrow[1] *= c1;
        mrow[0] = mn0; mrow[1] = mn1;
        #pragma unroll
        for (int nf = 0; nf < 8; nf++) {
            acc[nf][0] *= c0; acc[nf][1] *= c0;
            acc[nf][2] *= c1; acc[nf][3] *= c1;
        }
        uint32_t ph01[8], ph23[8];
        float rs0 = 0.f, rs1 = 0.f;
        #pragma unroll
        for (int nf = 0; nf < 8; nf++) {
            float p0 = __expf(sc[nf][0] - mn0), p1 = __expf(sc[nf][1] - mn0);
            float p2 = __expf(sc[nf][2] - mn1), p3 = __expf(sc[nf][3] - mn1);
            rs0 += p0 + p1; rs1 += p2 + p3;
            ph01[nf] = pack2bf(p0, p1);
            ph23[nf] = pack2bf(p2, p3);
        }
        #pragma unroll
        for (int o = 1; o <= 2; o <<= 1) {
            rs0 += __shfl_xor_sync(0xffffffffu, rs0, o);
            rs1 += __shfl_xor_sync(0xffffffffu, rs1, o);
        }
        lrow[0] += rs0; lrow[1] += rs1;

        CP_WAIT0(); __syncthreads();   // V ready

        #pragma unroll
        for (int ks = 0; ks < 4; ks++) {
            uint32_t aH[4] = {ph01[2*ks], ph23[2*ks], ph01[2*ks+1], ph23[2*ks+1]};
            #pragma unroll
            for (int np = 0; np < 4; np++) {
                uint32_t v0, v1, v2, v3;
                uint32_t ad = sb + AT_V +
                    (uint32_t)((16*ks + (sub & 1)*8 + lr) * 144 + ((sub >> 1)*8 + np*16)*2);
                ldsm_x4_t(v0, v1, v2, v3, ad);
                mma16816(acc[2*np],   aH, v0, v1);
                mma16816(acc[2*np+1], aH, v2, v3);
            }
        }
    }

    // ---- write ctx (bf16, merged-head layout) ----
    {
        float i0 = 1.f / lrow[0], i1 = 1.f / lrow[1];
        const int rl0 = l0 + 16*w + g, rl1 = rl0 + 8;
        #pragma unroll
        for (int nf = 0; nf < 8; nf++) {
            int col = nf*8 + t*2;
            size_t b0a = (((size_t)b * S_ + rl0) * H_ + h) * 64 + col;
            size_t b1a = (((size_t)b * S_ + rl1) * H_ + h) * 64 + col;
            *reinterpret_cast<bf162*>(g_ctx + b0a) = __floats2bfloat162_rn(
                save[nf][0] + acc[nf][0]*i0, save[nf][1] + acc[nf][1]*i0);
            *reinterpret_cast<bf162*>(g_ctx + b1a) = __floats2bfloat162_rn(
                save[nf][2] + acc[nf][2]*i1, save[nf][3] + acc[nf][3]*i1);
        }
    }
}

// ---------------- LayerNorm ----------------------
__global__ void k_ln(const float* __restrict__ ga, const float* __restrict__ be,
                     float* __restrict__ out) {
    const int row = blockIdx.x;
    const int tid = threadIdx.x;
    const float* y = g_Y + (size_t)row * DM_;
    float4 tv = *reinterpret_cast<const float4*>(y + tid * 4);
    float s  = tv.x + tv.y + tv.z + tv.w;
    float s2 = tv.x * tv.x + tv.y * tv.y + tv.z * tv.z + tv.w * tv.w;
    #pragma unroll
    for (int o = 16; o > 0; o >>= 1) {
        s  += __shfl_xor_sync(0xffffffffu, s,  o);
        s2 += __shfl_xor_sync(0xffffffffu, s2, o);
    }
    __shared__ float sh[16];
    int w = tid >> 5, lane = tid & 31;
    if (lane == 0) { sh[w] = s; sh[8 + w] = s2; }
    __syncthreads();
    if (tid == 0) {
        float S = 0.f, S2 = 0.f;
        #pragma unroll
        for (int i = 0; i < 8; i++) { S += sh[i]; S2 += sh[8 + i]; }
        sh[0] = S; sh[1] = S2;
    }
    __syncthreads();
    float mu  = sh[0] * (1.f / DM_);
    float var = sh[1] * (1.f / DM_) - mu * mu;
    float r   = rsqrtf(var + 1e-12f);
    int c = tid * 4;
    float4 gv = *reinterpret_cast<const float4*>(ga + c);
    float4 bv = *reinterpret_cast<const float4*>(be + c);
    float4 o;
    o.x = (tv.x - mu) * r * gv.x + bv.x;
    o.y = (tv.y - mu) * r * gv.y + bv.y;
    o.z = (tv.z - mu) * r * gv.z + bv.z;
    o.w = (tv.w - mu) * r * gv.w + bv.w;
    *reinterpret_cast<float4*>(out + (size_t)row * DM_ + c) = o;
}

// ---------------- launch ----------------------------------------------------
extern "C" void kernel_launch(void* const* d_in, const int* in_sizes, int n_in,
                              void* d_out, int out_size) {
    (void)in_sizes; (void)n_in; (void)out_size;
    const float* hs   = (const float*)d_in[0];
    const float* mask = (const float*)d_in[1];
    const float* enc  = (const float*)d_in[2];
    const float* Wq   = (const float*)d_in[3];
    const float* bq   = (const float*)d_in[4];
    const float* Wk   = (const float*)d_in[5];
    const float* bk   = (const float*)d_in[6];
    const float* Wv   = (const float*)d_in[7];
    const float* bv   = (const float*)d_in[8];
    const float* Wfk  = (const float*)d_in[9];
    const float* bfk  = (const float*)d_in[10];
    const float* Wfv  = (const float*)d_in[11];
    const float* bfv  = (const float*)d_in[12];
    const float* E    = (const float*)d_in[13];
    const float* Wo   = (const float*)d_in[14];
    const float* bo   = (const float*)d_in[15];
    const float* lg   = (const float*)d_in[16];
    const float* lb   = (const float*)d_in[17];
    float* out = (float*)d_out;

    static bool attr_set = false;
    if (!attr_set) {
        cudaFuncSetAttribute(k_attn, cudaFuncAttributeMaxDynamicSharedMemorySize, ATTN_SMEM_BYTES);
        cudaFuncSetAttribute(k_gemm, cudaFuncAttributeMaxDynamicSharedMemorySize, GEMM_SMEM_BYTES);
        attr_set = true;
    }

    k_cvt_all<<<10368, 256>>>(hs, enc, Wq, Wk, Wv, Wo, Wfk, Wfv, E);

    k_gemm<<<dim3(8, 32, 3), 256, GEMM_SMEM_BYTES>>>(bq, bk, bv, nullptr, 0);
    k_gemm<<<dim3(8, 16, 2), 256, GEMM_SMEM_BYTES>>>(bfk, bfv, nullptr, nullptr, 3);

    k_attn<<<dim3(16, 16, 4), 128, ATTN_SMEM_BYTES>>>(mask);

    k_gemm<<<dim3(8, 32, 1), 256, GEMM_SMEM_BYTES>>>(bo, nullptr, nullptr, hs, 5);
    k_ln<<<4096, 256>>>(lg, lb, out);
}